// round 1
// baseline (speedup 1.0000x reference)
#include <cuda_runtime.h>
#include <math.h>

#define Bq   4
#define Tq   512
#define Pq   3
#define HIDq 512
#define HDq  32
#define Hq   16
#define EXPq 512
#define Sq   1024
#define Dq   96      // P*HD, per-head dim

#define TT 32        // t rows per block
#define TS 32        // s cols per tile
#define RS 100       // padded smem row stride (96 + 4) to avoid bank conflicts

// Scratch (device globals: no allocations allowed)
__device__ float g_attn[Bq * Tq * Pq * HIDq];   // (B,T,P,HID) fp32, 12.6 MB
__device__ float g_inv[Bq * Tq];

// ---------------------------------------------------------------------------
// Kernel 1: fused gather + attention with online softmax.
// Block = (b, h, 32-row t tile). 256 threads: 8 warps, each warp owns 4 rows,
// 8 lanes per row, each lane owns 12 of the 96 head dims for PV accumulation.
// ---------------------------------------------------------------------------
__global__ __launch_bounds__(256) void attn_kernel(
    const float* __restrict__ q, const float* __restrict__ k,
    const float* __restrict__ v, const float* __restrict__ bias,
    const unsigned char* __restrict__ kpm, const int* __restrict__ outcell,
    const float* __restrict__ law, const unsigned char* __restrict__ emask)
{
    __shared__ float sQ[TT * RS];
    __shared__ float sK[TS * RS];
    __shared__ float sV[TS * RS];
    __shared__ float sP[TT * TS];
    __shared__ int   sTS[TS];
    __shared__ unsigned char sM[TS];

    const int b   = blockIdx.z;
    const int h   = blockIdx.y;
    const int t0  = blockIdx.x * TT;
    const int tid = threadIdx.x;
    const int warp = tid >> 5, lane = tid & 31;
    const int row = warp * 4 + (lane >> 3);   // 0..31
    const int sub = lane & 7;                 // 0..7
    const int t   = t0 + row;

    // Load Q tile (gathered head layout): sQ[r][d], d = p*32 + j
    for (int idx = tid; idx < TT * Dq; idx += 256) {
        int r = idx / Dq, d = idx - r * Dq;
        int p = d >> 5, j = d & 31;
        sQ[r * RS + d] = q[(((b * Tq + t0 + r) * Pq + p) << 9) + (h << 5) + j];
    }

    float m = -3.0e38f, l = 0.f;
    float acc[12];
#pragma unroll
    for (int i = 0; i < 12; i++) acc[i] = 0.f;

    for (int s0 = 0; s0 < Sq; s0 += TS) {
        __syncthreads();                      // protect sK/sV/sP reuse
        if (tid < TS) {
            int s = s0 + tid;
            int ts; unsigned char mm;
            if (s < Tq) { ts = s; mm = kpm[b * Tq + s]; }
            else        { int e = s - Tq; ts = outcell[b * EXPq + e]; mm = emask[b * EXPq + e]; }
            sTS[tid] = ts; sM[tid] = mm;
        }
        __syncthreads();
        // Gather K,V tile through outcell index
        for (int idx = tid; idx < TS * Dq; idx += 256) {
            int c = idx / Dq, d = idx - c * Dq;
            int p = d >> 5, j = d & 31;
            int ts = sTS[c];
            int off = (((b * Tq + ts) * Pq + p) << 9) + (h << 5) + j;
            sK[c * RS + d] = k[off];
            sV[c * RS + d] = v[off];
        }
        __syncthreads();

        // Scores: each lane computes 4 cols (sub, sub+8, sub+16, sub+24)
        float sc[4];
#pragma unroll
        for (int i = 0; i < 4; i++) sc[i] = 0.f;
        const float* qrow = &sQ[row * RS];
#pragma unroll
        for (int kk = 0; kk < Dq; kk += 4) {
            float4 qv = *(const float4*)(qrow + kk);
#pragma unroll
            for (int i = 0; i < 4; i++) {
                float4 kv = *(const float4*)(&sK[(sub + 8 * i) * RS + kk]);
                sc[i] += qv.x * kv.x + qv.y * kv.y + qv.z * kv.z + qv.w * kv.w;
            }
        }

        bool  dead[4];
        float lw4[4];
        float lmax = -3.0e38f;
#pragma unroll
        for (int i = 0; i < 4; i++) {
            int cl = sub + 8 * i;
            int s  = s0 + cl;
            float bs = bias[((long)((b * Hq + h) * Tq + t) << 10) + s];
            float lw = law[((long)(b * Tq + t) << 10) + s];
            float w  = sc[i] + bs;
            dead[i] = (sM[cl] != 0) | (lw <= 1e-5f);
            lw4[i]  = lw;
            sc[i]   = w;
            if (!dead[i]) lmax = fmaxf(lmax, w);
        }
#pragma unroll
        for (int o = 1; o < 8; o <<= 1)
            lmax = fmaxf(lmax, __shfl_xor_sync(0xffffffffu, lmax, o));

        float newm  = fmaxf(m, lmax);
        float scale = __expf(m - newm);
        float esum  = 0.f;
#pragma unroll
        for (int i = 0; i < 4; i++) {
            float e = dead[i] ? 0.f : __expf(sc[i] - newm);
            esum += e;
            sP[row * TS + sub + 8 * i] = e * lw4[i];   // fold p * law into PV
        }
#pragma unroll
        for (int o = 1; o < 8; o <<= 1)
            esum += __shfl_xor_sync(0xffffffffu, esum, o);
        l = l * scale + esum;
        m = newm;
#pragma unroll
        for (int i = 0; i < 12; i++) acc[i] *= scale;
        __syncwarp();                         // sP is row-private to this warp

        const int d0 = sub * 12;
#pragma unroll 4
        for (int c = 0; c < TS; c++) {
            float pv = sP[row * TS + c];
            const float4* vr = (const float4*)(&sV[c * RS + d0]); // d0 % 4 == 0
            float4 v0 = vr[0], v1 = vr[1], v2 = vr[2];
            acc[0] += pv * v0.x;  acc[1] += pv * v0.y;
            acc[2] += pv * v0.z;  acc[3] += pv * v0.w;
            acc[4] += pv * v1.x;  acc[5] += pv * v1.y;
            acc[6] += pv * v1.z;  acc[7] += pv * v1.w;
            acc[8] += pv * v2.x;  acc[9] += pv * v2.y;
            acc[10] += pv * v2.z; acc[11] += pv * v2.w;
        }
    }

    float rl = (l > 0.f) ? 1.f / l : 0.f;
    const int d0 = sub * 12;
#pragma unroll
    for (int i = 0; i < 12; i++) {
        int d = d0 + i;
        int p = d >> 5, j = d & 31;
        g_attn[(((b * Tq + t) * Pq + p) << 9) + (h << 5) + j] = acc[i] * rl;
    }
}

// ---------------------------------------------------------------------------
// Kernel 2: inv = rsqrt( sum_{p,d} attn^2 / HID + eps ) per (b,t)
// ---------------------------------------------------------------------------
__global__ __launch_bounds__(128) void inv_kernel()
{
    const int bt = blockIdx.x;
    const float* a = &g_attn[bt * Pq * HIDq];
    const int tid = threadIdx.x;
    float s = 0.f;
    for (int i = tid; i < Pq * HIDq; i += 128) { float x = a[i]; s = fmaf(x, x, s); }
#pragma unroll
    for (int o = 16; o; o >>= 1) s += __shfl_xor_sync(0xffffffffu, s, o);
    __shared__ float ws[4];
    if ((tid & 31) == 0) ws[tid >> 5] = s;
    __syncthreads();
    if (tid == 0) {
        float tot = ws[0] + ws[1] + ws[2] + ws[3];
        g_inv[bt] = rsqrtf(tot * (1.0f / (float)HIDq) + 1e-3f);
    }
}

// ---------------------------------------------------------------------------
// Kernel 3: out[row, o] = sum_d (attn[row,d]*lnw[d]*inv[row/3]) * W[o,d]
// 64x64 tile, BK=16, 256 threads, 4x4 per thread.
// ---------------------------------------------------------------------------
__global__ __launch_bounds__(256) void proj_kernel(
    const float* __restrict__ W, const float* __restrict__ lnw,
    float* __restrict__ out)
{
    __shared__ float Xs[16][64 + 4];
    __shared__ float Ws[16][64 + 4];
    const int bm = blockIdx.x, bn = blockIdx.y;
    const int tid = threadIdx.x;
    const int tx = tid & 15, ty = tid >> 4;
    const int lm = tid >> 2;            // 0..63
    const int lk = (tid & 3) << 2;      // 0,4,8,12
    const int row = bm * 64 + lm;
    const float invv = g_inv[row / 3];

    float acc[4][4];
#pragma unroll
    for (int i = 0; i < 4; i++)
#pragma unroll
        for (int j = 0; j < 4; j++) acc[i][j] = 0.f;

    for (int k0 = 0; k0 < HIDq; k0 += 16) {
        float4 xv = *(const float4*)&g_attn[row * HIDq + k0 + lk];
        float4 lw = *(const float4*)&lnw[k0 + lk];
        Xs[lk + 0][lm] = xv.x * lw.x * invv;
        Xs[lk + 1][lm] = xv.y * lw.y * invv;
        Xs[lk + 2][lm] = xv.z * lw.z * invv;
        Xs[lk + 3][lm] = xv.w * lw.w * invv;
        float4 wv = *(const float4*)&W[(bn * 64 + lm) * HIDq + k0 + lk];
        Ws[lk + 0][lm] = wv.x;
        Ws[lk + 1][lm] = wv.y;
        Ws[lk + 2][lm] = wv.z;
        Ws[lk + 3][lm] = wv.w;
        __syncthreads();
#pragma unroll
        for (int kk = 0; kk < 16; kk++) {
            float rm[4], rn[4];
#pragma unroll
            for (int i = 0; i < 4; i++) rm[i] = Xs[kk][ty * 4 + i];
#pragma unroll
            for (int j = 0; j < 4; j++) rn[j] = Ws[kk][tx * 4 + j];
#pragma unroll
            for (int i = 0; i < 4; i++)
#pragma unroll
                for (int j = 0; j < 4; j++)
                    acc[i][j] = fmaf(rm[i], rn[j], acc[i][j]);
        }
        __syncthreads();
    }
#pragma unroll
    for (int i = 0; i < 4; i++) {
        int r = bm * 64 + ty * 4 + i;
        float4 o4 = make_float4(acc[i][0], acc[i][1], acc[i][2], acc[i][3]);
        *(float4*)&out[r * HIDq + bn * 64 + tx * 4] = o4;
    }
}

// ---------------------------------------------------------------------------
extern "C" void kernel_launch(void* const* d_in, const int* in_sizes, int n_in,
                              void* d_out, int out_size)
{
    const float* q    = (const float*)d_in[0];
    const float* k    = (const float*)d_in[1];
    const float* v    = (const float*)d_in[2];
    const float* bias = (const float*)d_in[3];
    const unsigned char* kpm   = (const unsigned char*)d_in[4];
    const int*   outcell       = (const int*)d_in[5];
    const float* law  = (const float*)d_in[6];
    const unsigned char* emask = (const unsigned char*)d_in[7];
    const float* W    = (const float*)d_in[8];
    const float* lnw  = (const float*)d_in[9];
    float* out = (float*)d_out;

    dim3 g1(Tq / TT, Hq, Bq);
    attn_kernel<<<g1, 256>>>(q, k, v, bias, kpm, outcell, law, emask);
    inv_kernel<<<Bq * Tq, 128>>>();
    dim3 g3((Bq * Tq * Pq) / 64, HIDq / 64);
    proj_kernel<<<g3, 256>>>(W, lnw, out);
}

// round 3
// speedup vs baseline: 1.6395x; 1.6395x over previous
#include <cuda_runtime.h>
#include <math.h>

#define Bq   4
#define Tq   512
#define Pq   3
#define HIDq 512
#define Hq   16
#define EXPq 512
#define Sq   1024
#define Dq   96

#define TT   64      // t rows per block (4 warps x 16)
#define TS   32      // s cols per tile
#define KSN  12      // Dq/8 k-steps for QK
#define NFV  12      // Dq/8 n-frags for PV
#define SPst 36      // P smem row stride (floats)

// Dynamic smem layout (bytes)
#define OFF_K   0                 // uint4 [32][13][4]  : 26,624
#define OFF_V   26624             // uint4 [16][98]     : 25,088
#define OFF_PH  51712             // float [64][36]     :  9,216
#define OFF_PL  60928             // float [64][36]     :  9,216
#define OFF_TS  70144             // int   [32]
#define OFF_DD  70272             // uchar [32]
#define SMEMSZ  70400

__device__ float g_attn[Bq * Tq * Pq * HIDq];
__device__ float g_inv[Bq * Tq];

__device__ __forceinline__ unsigned f2tf(float f) {
    unsigned u; asm("cvt.rna.tf32.f32 %0,%1;" : "=r"(u) : "f"(f)); return u;
}
__device__ __forceinline__ void mma_tf32(float* c,
    unsigned a0, unsigned a1, unsigned a2, unsigned a3,
    unsigned b0, unsigned b1)
{
    asm volatile(
        "mma.sync.aligned.m16n8k8.row.col.f32.tf32.tf32.f32 "
        "{%0,%1,%2,%3},{%4,%5,%6,%7},{%8,%9},{%0,%1,%2,%3};"
        : "+f"(c[0]), "+f"(c[1]), "+f"(c[2]), "+f"(c[3])
        : "r"(a0), "r"(a1), "r"(a2), "r"(a3), "r"(b0), "r"(b1));
}

// ---------------------------------------------------------------------------
// Fused gather + flash attention, 3xTF32 tensor cores (fp32-accurate).
// Block = (b, h, 64-row t tile), 128 threads / 4 warps; warp owns 16 rows for
// all s columns -> softmax warp-local.
// ---------------------------------------------------------------------------
__global__ __launch_bounds__(128, 2) void attn_kernel(
    const float* __restrict__ q, const float* __restrict__ k,
    const float* __restrict__ v, const float* __restrict__ bias,
    const unsigned char* __restrict__ kpm, const int* __restrict__ outcell,
    const float* __restrict__ law, const unsigned char* __restrict__ emask)
{
    extern __shared__ char smembuf[];
    uint4*         sK4   = (uint4*)(smembuf + OFF_K);   // [(c*52 + ks*4 + tig)]
    uint4*         sV4   = (uint4*)(smembuf + OFF_V);   // [((ks*4+tig)*98 + col)]
    unsigned*      sKu   = (unsigned*)sK4;
    unsigned*      sVu   = (unsigned*)sV4;
    float*         Ph    = (float*)(smembuf + OFF_PH);
    float*         Pl    = (float*)(smembuf + OFF_PL);
    int*           sTS   = (int*)(smembuf + OFF_TS);
    unsigned char* sDead = (unsigned char*)(smembuf + OFF_DD);

    const int b  = blockIdx.z, h = blockIdx.y;
    const int t0 = blockIdx.x * TT;
    const int tid  = threadIdx.x;
    const int warp = tid >> 5, lane = tid & 31;
    const int gid  = lane >> 2, tig = lane & 3;
    const int rowBase = warp * 16;
    const int rlo = rowBase + gid, rhi = rlo + 8;
    const int tlo = t0 + rlo,      thi = t0 + rhi;

    // Preload Q A-fragments (hi/lo split) into registers.
    unsigned qh[KSN][4], ql[KSN][4];
#pragma unroll
    for (int ks = 0; ks < KSN; ks++) {
        int d0 = ks * 8 + tig, d1 = d0 + 4;
        float q00 = q[((b * Tq + tlo) * Pq + (d0 >> 5)) * HIDq + h * 32 + (d0 & 31)];
        float q10 = q[((b * Tq + thi) * Pq + (d0 >> 5)) * HIDq + h * 32 + (d0 & 31)];
        float q01 = q[((b * Tq + tlo) * Pq + (d1 >> 5)) * HIDq + h * 32 + (d1 & 31)];
        float q11 = q[((b * Tq + thi) * Pq + (d1 >> 5)) * HIDq + h * 32 + (d1 & 31)];
        qh[ks][0] = f2tf(q00); ql[ks][0] = f2tf(q00 - __uint_as_float(qh[ks][0]));
        qh[ks][1] = f2tf(q10); ql[ks][1] = f2tf(q10 - __uint_as_float(qh[ks][1]));
        qh[ks][2] = f2tf(q01); ql[ks][2] = f2tf(q01 - __uint_as_float(qh[ks][2]));
        qh[ks][3] = f2tf(q11); ql[ks][3] = f2tf(q11 - __uint_as_float(qh[ks][3]));
    }

    float m_lo = -3.0e38f, m_hi = -3.0e38f, l_lo = 0.f, l_hi = 0.f;
    float acc[NFV][4];
#pragma unroll
    for (int nf = 0; nf < NFV; nf++)
#pragma unroll
        for (int i = 0; i < 4; i++) acc[nf][i] = 0.f;

    for (int s0 = 0; s0 < Sq; s0 += TS) {
        __syncthreads();                       // protect sK/sV reuse
        if (tid < TS) {
            int s = s0 + tid; int ts; unsigned char mm;
            if (s < Tq) { ts = s; mm = kpm[b * Tq + s]; }
            else { int e = s - Tq; ts = outcell[b * EXPq + e]; mm = emask[b * EXPq + e]; }
            sTS[tid] = ts; sDead[tid] = mm;
        }
        __syncthreads();

        // Gather K,V; split hi/lo; store into fragment-native layouts.
        for (int i = tid; i < TS * 24; i += 128) {        // 24 float4 per s-col
            int c = i / 24, j4 = i - c * 24;
            int d = j4 * 4;
            int ts = sTS[c];
            int base = ((b * Tq + ts) * Pq + (d >> 5)) * HIDq + h * 32 + (d & 31);
            float4 kv = *(const float4*)&k[base];
            float4 vv = *(const float4*)&v[base];
            int cks = c >> 3, ctig = c & 3, chalf = (c >> 2) & 1;
            int vrow = (cks * 4 + ctig) * 98;
            float ke[4] = {kv.x, kv.y, kv.z, kv.w};
            float ve[4] = {vv.x, vv.y, vv.z, vv.w};
#pragma unroll
            for (int e2 = 0; e2 < 4; e2++) {
                int dd = d + e2;
                // K: element (c, dd)
                int ks2 = dd >> 3, e = dd & 7, tg = e & 3, hf = e >> 2;
                unsigned khh = f2tf(ke[e2]);
                unsigned kll = f2tf(ke[e2] - __uint_as_float(khh));
                int kbase = ((c * 52 + ks2 * 4 + tg) << 2);
                sKu[kbase + hf]     = khh;
                sKu[kbase + 2 + hf] = kll;
                // V: element (row=c, col=dd)
                unsigned vhh = f2tf(ve[e2]);
                unsigned vll = f2tf(ve[e2] - __uint_as_float(vhh));
                int vbase = ((vrow + dd) << 2);
                sVu[vbase + chalf]     = vhh;
                sVu[vbase + 2 + chalf] = vll;
            }
        }
        __syncthreads();

        // ---- scores: C[16x32] per warp, 3xTF32
        float sc[4][4];
#pragma unroll
        for (int nf = 0; nf < 4; nf++)
#pragma unroll
            for (int i = 0; i < 4; i++) sc[nf][i] = 0.f;
#pragma unroll
        for (int ks = 0; ks < KSN; ks++) {
#pragma unroll
            for (int nf = 0; nf < 4; nf++) {
                uint4 bb = sK4[(nf * 8 + gid) * 52 + ks * 4 + tig];
                mma_tf32(sc[nf], qh[ks][0], qh[ks][1], qh[ks][2], qh[ks][3], bb.x, bb.y);
                mma_tf32(sc[nf], ql[ks][0], ql[ks][1], ql[ks][2], ql[ks][3], bb.x, bb.y);
                mma_tf32(sc[nf], qh[ks][0], qh[ks][1], qh[ks][2], qh[ks][3], bb.z, bb.w);
            }
        }

        // ---- bias + masks + online softmax (warp-local)
        float pw[4][4];
        float lmax_lo = -3.0e38f, lmax_hi = -3.0e38f;
#pragma unroll
        for (int nf = 0; nf < 4; nf++) {
            int colL = nf * 8 + 2 * tig;
            int col  = s0 + colL;
            float2 blo = *(const float2*)&bias[((b * Hq + h) * Tq + tlo) * Sq + col];
            float2 bhi = *(const float2*)&bias[((b * Hq + h) * Tq + thi) * Sq + col];
            float2 wlo = *(const float2*)&law [(b * Tq + tlo) * Sq + col];
            float2 whi = *(const float2*)&law [(b * Tq + thi) * Sq + col];
            unsigned char d0 = sDead[colL], d1 = sDead[colL + 1];

            float x, lw;
            x = sc[nf][0] + blo.x; lw = wlo.x;
            if (d0 || lw <= 1e-5f) { x = -3.0e38f; lw = 0.f; }
            sc[nf][0] = x; pw[nf][0] = lw; lmax_lo = fmaxf(lmax_lo, x);
            x = sc[nf][1] + blo.y; lw = wlo.y;
            if (d1 || lw <= 1e-5f) { x = -3.0e38f; lw = 0.f; }
            sc[nf][1] = x; pw[nf][1] = lw; lmax_lo = fmaxf(lmax_lo, x);
            x = sc[nf][2] + bhi.x; lw = whi.x;
            if (d0 || lw <= 1e-5f) { x = -3.0e38f; lw = 0.f; }
            sc[nf][2] = x; pw[nf][2] = lw; lmax_hi = fmaxf(lmax_hi, x);
            x = sc[nf][3] + bhi.y; lw = whi.y;
            if (d1 || lw <= 1e-5f) { x = -3.0e38f; lw = 0.f; }
            sc[nf][3] = x; pw[nf][3] = lw; lmax_hi = fmaxf(lmax_hi, x);
        }
#pragma unroll
        for (int o = 1; o < 4; o <<= 1) {
            lmax_lo = fmaxf(lmax_lo, __shfl_xor_sync(0xffffffffu, lmax_lo, o));
            lmax_hi = fmaxf(lmax_hi, __shfl_xor_sync(0xffffffffu, lmax_hi, o));
        }
        float nm_lo = fmaxf(m_lo, lmax_lo), nm_hi = fmaxf(m_hi, lmax_hi);
        float sl_lo = __expf(m_lo - nm_lo),  sl_hi = __expf(m_hi - nm_hi);
        m_lo = nm_lo; m_hi = nm_hi;

        float es_lo = 0.f, es_hi = 0.f;
#pragma unroll
        for (int nf = 0; nf < 4; nf++) {
            float e0 = __expf(sc[nf][0] - nm_lo); es_lo += e0;
            float e1 = __expf(sc[nf][1] - nm_lo); es_lo += e1;
            float e2 = __expf(sc[nf][2] - nm_hi); es_hi += e2;
            float e3 = __expf(sc[nf][3] - nm_hi); es_hi += e3;
            float p0 = e0 * pw[nf][0], p1 = e1 * pw[nf][1];
            float p2 = e2 * pw[nf][2], p3 = e3 * pw[nf][3];
            unsigned h0 = f2tf(p0), h1 = f2tf(p1), h2 = f2tf(p2), h3 = f2tf(p3);
            int pc = nf * 8 + 2 * tig;
            *(uint2*)&Ph[rlo * SPst + pc] = make_uint2(h0, h1);
            *(uint2*)&Ph[rhi * SPst + pc] = make_uint2(h2, h3);
            *(uint2*)&Pl[rlo * SPst + pc] = make_uint2(
                f2tf(p0 - __uint_as_float(h0)), f2tf(p1 - __uint_as_float(h1)));
            *(uint2*)&Pl[rhi * SPst + pc] = make_uint2(
                f2tf(p2 - __uint_as_float(h2)), f2tf(p3 - __uint_as_float(h3)));
        }
#pragma unroll
        for (int o = 1; o < 4; o <<= 1) {
            es_lo += __shfl_xor_sync(0xffffffffu, es_lo, o);
            es_hi += __shfl_xor_sync(0xffffffffu, es_hi, o);
        }
        l_lo = l_lo * sl_lo + es_lo;
        l_hi = l_hi * sl_hi + es_hi;
#pragma unroll
        for (int nf = 0; nf < NFV; nf++) {
            acc[nf][0] *= sl_lo; acc[nf][1] *= sl_lo;
            acc[nf][2] *= sl_hi; acc[nf][3] *= sl_hi;
        }
        __syncwarp();                          // P rows are warp-private

        // ---- PV: acc[16x96] += P[16x32] * V[32x96], 3xTF32
        const unsigned* Phu = (const unsigned*)Ph;
        const unsigned* Plu = (const unsigned*)Pl;
#pragma unroll
        for (int ks = 0; ks < 4; ks++) {
            int pc = ks * 8 + tig;
            unsigned ah0 = Phu[rlo * SPst + pc],     ah1 = Phu[rhi * SPst + pc];
            unsigned ah2 = Phu[rlo * SPst + pc + 4], ah3 = Phu[rhi * SPst + pc + 4];
            unsigned al0 = Plu[rlo * SPst + pc],     al1 = Plu[rhi * SPst + pc];
            unsigned al2 = Plu[rlo * SPst + pc + 4], al3 = Plu[rhi * SPst + pc + 4];
#pragma unroll
            for (int nf = 0; nf < NFV; nf++) {
                uint4 bb = sV4[(ks * 4 + tig) * 98 + nf * 8 + gid];
                mma_tf32(acc[nf], ah0, ah1, ah2, ah3, bb.x, bb.y);
                mma_tf32(acc[nf], al0, al1, al2, al3, bb.x, bb.y);
                mma_tf32(acc[nf], ah0, ah1, ah2, ah3, bb.z, bb.w);
            }
        }
        __syncwarp();                          // next-iter P writes vs reads
    }

    float rl_lo = (l_lo > 0.f) ? 1.f / l_lo : 0.f;
    float rl_hi = (l_hi > 0.f) ? 1.f / l_hi : 0.f;
#pragma unroll
    for (int nf = 0; nf < NFV; nf++) {
        int d = nf * 8 + 2 * tig;
        int p = d >> 5, j = d & 31;
        *(float2*)&g_attn[((b * Tq + tlo) * Pq + p) * HIDq + h * 32 + j] =
            make_float2(acc[nf][0] * rl_lo, acc[nf][1] * rl_lo);
        *(float2*)&g_attn[((b * Tq + thi) * Pq + p) * HIDq + h * 32 + j] =
            make_float2(acc[nf][2] * rl_hi, acc[nf][3] * rl_hi);
    }
}

// ---------------------------------------------------------------------------
__global__ __launch_bounds__(128) void inv_kernel()
{
    const int bt = blockIdx.x;
    const float* a = &g_attn[bt * Pq * HIDq];
    const int tid = threadIdx.x;
    float s = 0.f;
    for (int i = tid; i < Pq * HIDq; i += 128) { float x = a[i]; s = fmaf(x, x, s); }
#pragma unroll
    for (int o = 16; o; o >>= 1) s += __shfl_xor_sync(0xffffffffu, s, o);
    __shared__ float ws[4];
    if ((tid & 31) == 0) ws[tid >> 5] = s;
    __syncthreads();
    if (tid == 0) {
        float tot = ws[0] + ws[1] + ws[2] + ws[3];
        g_inv[bt] = rsqrtf(tot * (1.0f / (float)HIDq) + 1e-3f);
    }
}

// ---------------------------------------------------------------------------
__global__ __launch_bounds__(256) void proj_kernel(
    const float* __restrict__ W, const float* __restrict__ lnw,
    float* __restrict__ out)
{
    __shared__ float Xs[16][64 + 4];
    __shared__ float Ws[16][64 + 4];
    const int bm = blockIdx.x, bn = blockIdx.y;
    const int tid = threadIdx.x;
    const int tx = tid & 15, ty = tid >> 4;
    const int lm = tid >> 2;
    const int lk = (tid & 3) << 2;
    const int row = bm * 64 + lm;
    const float invv = g_inv[row / 3];

    float acc[4][4];
#pragma unroll
    for (int i = 0; i < 4; i++)
#pragma unroll
        for (int j = 0; j < 4; j++) acc[i][j] = 0.f;

    for (int k0 = 0; k0 < HIDq; k0 += 16) {
        float4 xv = *(const float4*)&g_attn[row * HIDq + k0 + lk];
        float4 lw = *(const float4*)&lnw[k0 + lk];
        Xs[lk + 0][lm] = xv.x * lw.x * invv;
        Xs[lk + 1][lm] = xv.y * lw.y * invv;
        Xs[lk + 2][lm] = xv.z * lw.z * invv;
        Xs[lk + 3][lm] = xv.w * lw.w * invv;
        float4 wv = *(const float4*)&W[(bn * 64 + lm) * HIDq + k0 + lk];
        Ws[lk + 0][lm] = wv.x;
        Ws[lk + 1][lm] = wv.y;
        Ws[lk + 2][lm] = wv.z;
        Ws[lk + 3][lm] = wv.w;
        __syncthreads();
#pragma unroll
        for (int kk = 0; kk < 16; kk++) {
            float rm[4], rn[4];
#pragma unroll
            for (int i = 0; i < 4; i++) rm[i] = Xs[kk][ty * 4 + i];
#pragma unroll
            for (int j = 0; j < 4; j++) rn[j] = Ws[kk][tx * 4 + j];
#pragma unroll
            for (int i = 0; i < 4; i++)
#pragma unroll
                for (int j = 0; j < 4; j++)
                    acc[i][j] = fmaf(rm[i], rn[j], acc[i][j]);
        }
        __syncthreads();
    }
#pragma unroll
    for (int i = 0; i < 4; i++) {
        int r = bm * 64 + ty * 4 + i;
        *(float4*)&out[r * HIDq + bn * 64 + tx * 4] =
            make_float4(acc[i][0], acc[i][1], acc[i][2], acc[i][3]);
    }
}

// ---------------------------------------------------------------------------
extern "C" void kernel_launch(void* const* d_in, const int* in_sizes, int n_in,
                              void* d_out, int out_size)
{
    const float* q    = (const float*)d_in[0];
    const float* k    = (const float*)d_in[1];
    const float* v    = (const float*)d_in[2];
    const float* bias = (const float*)d_in[3];
    const unsigned char* kpm   = (const unsigned char*)d_in[4];
    const int*   outcell       = (const int*)d_in[5];
    const float* law  = (const float*)d_in[6];
    const unsigned char* emask = (const unsigned char*)d_in[7];
    const float* W    = (const float*)d_in[8];
    const float* lnw  = (const float*)d_in[9];
    float* out = (float*)d_out;

    cudaFuncSetAttribute(attn_kernel,
        cudaFuncAttributeMaxDynamicSharedMemorySize, SMEMSZ);

    dim3 g1(Tq / TT, Hq, Bq);
    attn_kernel<<<g1, 128, SMEMSZ>>>(q, k, v, bias, kpm, outcell, law, emask);
    inv_kernel<<<Bq * Tq, 128>>>();
    dim3 g3((Bq * Tq * Pq) / 64, HIDq / 64);
    proj_kernel<<<g3, 256>>>(W, lnw, out);
}

// round 4
// speedup vs baseline: 2.3686x; 1.4447x over previous
#include <cuda_runtime.h>
#include <math.h>

#define Bq   4
#define Tq   512
#define Pq   3
#define HIDq 512
#define Hq   16
#define EXPq 512
#define Sq   1024
#define Dq   96

#define TT   64      // t rows per block (4 warps x 16)
#define TS   32      // s cols per tile
#define KSN  12      // Dq/8 k-steps for QK
#define NFV  12      // Dq/8 n-frags for PV
#define SPst 36      // P smem row stride (floats)

// Dynamic smem layout (bytes)
#define OFF_K   0                 // uint4 [32 cols][52]  (48 used + pad) : 26,624
#define OFF_V   26624             // uint2 [32 rows][100] (96 used + pad) : 25,600
#define OFF_PH  52224             // float [64][36] : 9,216
#define OFF_PL  61440             // float [64][36] : 9,216
#define OFF_TS  70656             // int   [32]
#define OFF_DD  70784             // uchar [32]
#define SMEMSZ  70912

// Pre-split K/V in fragment-native layouts:
// g_K[(b*T+t)*H+h] : 48 uint4, index ks*4+tig = (hi(d), hi(d+4), lo(d), lo(d+4)), d=8*ks+tig
// g_V[(b*T+t)*H+h] : 96 uint2, index n = (hi, lo)
__device__ uint4 g_K[Bq * Tq * Hq * 48];
__device__ uint2 g_V[Bq * Tq * Hq * 96];
__device__ float g_attn[Bq * Tq * Pq * HIDq];
__device__ float g_inv[Bq * Tq];

__device__ __forceinline__ unsigned f2tf(float f) {
    unsigned u; asm("cvt.rna.tf32.f32 %0,%1;" : "=r"(u) : "f"(f)); return u;
}
__device__ __forceinline__ void mma_tf32(float* c,
    unsigned a0, unsigned a1, unsigned a2, unsigned a3,
    unsigned b0, unsigned b1)
{
    asm volatile(
        "mma.sync.aligned.m16n8k8.row.col.f32.tf32.tf32.f32 "
        "{%0,%1,%2,%3},{%4,%5,%6,%7},{%8,%9},{%0,%1,%2,%3};"
        : "+f"(c[0]), "+f"(c[1]), "+f"(c[2]), "+f"(c[3])
        : "r"(a0), "r"(a1), "r"(a2), "r"(a3), "r"(b0), "r"(b1));
}
__device__ __forceinline__ void cpa16(unsigned dst, const void* src) {
    asm volatile("cp.async.cg.shared.global [%0], [%1], 16;\n" :: "r"(dst), "l"(src));
}

// ---------------------------------------------------------------------------
// Pre-split kernel: one-time tf32 hi/lo decomposition + head-gather transpose.
// unit u<12: K kstep (8 elems -> 4 uint4); u>=12: V 4-elem group -> 4 uint2.
// ---------------------------------------------------------------------------
__global__ __launch_bounds__(256) void presplit_kernel(
    const float* __restrict__ k, const float* __restrict__ v)
{
    int gidx = blockIdx.x * 256 + threadIdx.x;
    const int U = 36;
    if (gidx >= Bq * Tq * Hq * U) return;
    int u = gidx % U;
    int bth = gidx / U;          // (b*T+t)*H + h
    int h = bth % Hq;
    int bt = bth / Hq;           // b*T + t

    if (u < 12) {
        int ks = u, d = ks * 8;
        int p = d >> 5, j = d & 31;
        const float* src = &k[(bt * Pq + p) * HIDq + h * 32 + j];
        float4 x0 = *(const float4*)src;
        float4 x1 = *(const float4*)(src + 4);
        float e[8] = {x0.x, x0.y, x0.z, x0.w, x1.x, x1.y, x1.z, x1.w};
        uint4* dst = &g_K[bth * 48 + ks * 4];
#pragma unroll
        for (int tg = 0; tg < 4; tg++) {
            unsigned h0 = f2tf(e[tg]),     h1 = f2tf(e[tg + 4]);
            unsigned l0 = f2tf(e[tg]     - __uint_as_float(h0));
            unsigned l1 = f2tf(e[tg + 4] - __uint_as_float(h1));
            dst[tg] = make_uint4(h0, h1, l0, l1);
        }
    } else {
        int d = (u - 12) * 4;
        int p = d >> 5, j = d & 31;
        float4 x = *(const float4*)&v[(bt * Pq + p) * HIDq + h * 32 + j];
        float e[4] = {x.x, x.y, x.z, x.w};
        uint2* dst = &g_V[bth * 96 + d];
#pragma unroll
        for (int t2 = 0; t2 < 4; t2++) {
            unsigned hh = f2tf(e[t2]);
            dst[t2] = make_uint2(hh, f2tf(e[t2] - __uint_as_float(hh)));
        }
    }
}

// ---------------------------------------------------------------------------
// Fused gather + flash attention, 3xTF32 (fp32-accurate), cp.async tile copy.
// ---------------------------------------------------------------------------
__global__ __launch_bounds__(128, 2) void attn_kernel(
    const float* __restrict__ q, const float* __restrict__ bias,
    const unsigned char* __restrict__ kpm, const int* __restrict__ outcell,
    const float* __restrict__ law, const unsigned char* __restrict__ emask)
{
    extern __shared__ __align__(16) char smembuf[];
    const uint4*   sK4   = (const uint4*)(smembuf + OFF_K);   // [c*52 + ks*4+tig]
    const uint2*   sV2   = (const uint2*)(smembuf + OFF_V);   // [row*100 + n]
    float*         Ph    = (float*)(smembuf + OFF_PH);
    float*         Pl    = (float*)(smembuf + OFF_PL);
    int*           sTS   = (int*)(smembuf + OFF_TS);
    unsigned char* sDead = (unsigned char*)(smembuf + OFF_DD);
    unsigned sbase;
    { unsigned long long p0 = __cvta_generic_to_shared(smembuf); sbase = (unsigned)p0; }

    const int b  = blockIdx.z, h = blockIdx.y;
    const int t0 = blockIdx.x * TT;
    const int tid  = threadIdx.x;
    const int warp = tid >> 5, lane = tid & 31;
    const int gid  = lane >> 2, tig = lane & 3;
    const int rowBase = warp * 16;
    const int rlo = rowBase + gid, rhi = rlo + 8;
    const int tlo = t0 + rlo,      thi = t0 + rhi;

    // Preload Q A-fragments (hi/lo) into registers (reused for all 32 s-tiles)
    unsigned qh[KSN][4], ql[KSN][4];
#pragma unroll
    for (int ks = 0; ks < KSN; ks++) {
        int d0 = ks * 8 + tig, d1 = d0 + 4;
        float q00 = q[((b * Tq + tlo) * Pq + (d0 >> 5)) * HIDq + h * 32 + (d0 & 31)];
        float q10 = q[((b * Tq + thi) * Pq + (d0 >> 5)) * HIDq + h * 32 + (d0 & 31)];
        float q01 = q[((b * Tq + tlo) * Pq + (d1 >> 5)) * HIDq + h * 32 + (d1 & 31)];
        float q11 = q[((b * Tq + thi) * Pq + (d1 >> 5)) * HIDq + h * 32 + (d1 & 31)];
        qh[ks][0] = f2tf(q00); ql[ks][0] = f2tf(q00 - __uint_as_float(qh[ks][0]));
        qh[ks][1] = f2tf(q10); ql[ks][1] = f2tf(q10 - __uint_as_float(qh[ks][1]));
        qh[ks][2] = f2tf(q01); ql[ks][2] = f2tf(q01 - __uint_as_float(qh[ks][2]));
        qh[ks][3] = f2tf(q11); ql[ks][3] = f2tf(q11 - __uint_as_float(qh[ks][3]));
    }

    float m_lo = -3.0e38f, m_hi = -3.0e38f, l_lo = 0.f, l_hi = 0.f;
    float acc[NFV][4];
#pragma unroll
    for (int nf = 0; nf < NFV; nf++)
#pragma unroll
        for (int i = 0; i < 4; i++) acc[nf][i] = 0.f;

    for (int s0 = 0; s0 < Sq; s0 += TS) {
        __syncthreads();                       // protect sK/sV/sTS reuse
        if (tid < TS) {
            int s = s0 + tid; int ts; unsigned char mm;
            if (s < Tq) { ts = s; mm = kpm[b * Tq + s]; }
            else { int e = s - Tq; ts = outcell[b * EXPq + e]; mm = emask[b * EXPq + e]; }
            sTS[tid] = ts; sDead[tid] = mm;
        }
        __syncthreads();

        // Tile copy: pre-split fragment rows via cp.async (no cvt, no scatter)
        for (int i = tid; i < 1536; i += 128) {           // K: 32 cols x 48 x 16B
            int c = i / 48, f = i - c * 48;
            const uint4* src = &g_K[((b * Tq + sTS[c]) * Hq + h) * 48 + f];
            cpa16(sbase + OFF_K + c * 832 + f * 16, src);
        }
        for (int i = tid; i < 1536; i += 128) {           // V: 32 rows x 48 x 16B
            int c = i / 48, f = i - c * 48;
            const char* src = (const char*)&g_V[((b * Tq + sTS[c]) * Hq + h) * 96] + f * 16;
            cpa16(sbase + OFF_V + c * 800 + f * 16, src);
        }
        asm volatile("cp.async.commit_group;\ncp.async.wait_group 0;\n" ::: "memory");
        __syncthreads();

        // ---- scores: C[16x32] per warp, 3xTF32
        float sc[4][4];
#pragma unroll
        for (int nf = 0; nf < 4; nf++)
#pragma unroll
            for (int i = 0; i < 4; i++) sc[nf][i] = 0.f;
#pragma unroll
        for (int ks = 0; ks < KSN; ks++) {
#pragma unroll
            for (int nf = 0; nf < 4; nf++) {
                uint4 bb = sK4[(nf * 8 + gid) * 52 + ks * 4 + tig];
                mma_tf32(sc[nf], qh[ks][0], qh[ks][1], qh[ks][2], qh[ks][3], bb.x, bb.y);
                mma_tf32(sc[nf], ql[ks][0], ql[ks][1], ql[ks][2], ql[ks][3], bb.x, bb.y);
                mma_tf32(sc[nf], qh[ks][0], qh[ks][1], qh[ks][2], qh[ks][3], bb.z, bb.w);
            }
        }

        // ---- bias + masks + online softmax (warp-local)
        float pw[4][4];
        float lmax_lo = -3.0e38f, lmax_hi = -3.0e38f;
#pragma unroll
        for (int nf = 0; nf < 4; nf++) {
            int colL = nf * 8 + 2 * tig;
            int col  = s0 + colL;
            float2 blo = *(const float2*)&bias[((b * Hq + h) * Tq + tlo) * Sq + col];
            float2 bhi = *(const float2*)&bias[((b * Hq + h) * Tq + thi) * Sq + col];
            float2 wlo = *(const float2*)&law [(b * Tq + tlo) * Sq + col];
            float2 whi = *(const float2*)&law [(b * Tq + thi) * Sq + col];
            unsigned char d0 = sDead[colL], d1 = sDead[colL + 1];

            float x, lw;
            x = sc[nf][0] + blo.x; lw = wlo.x;
            if (d0 || lw <= 1e-5f) { x = -3.0e38f; lw = 0.f; }
            sc[nf][0] = x; pw[nf][0] = lw; lmax_lo = fmaxf(lmax_lo, x);
            x = sc[nf][1] + blo.y; lw = wlo.y;
            if (d1 || lw <= 1e-5f) { x = -3.0e38f; lw = 0.f; }
            sc[nf][1] = x; pw[nf][1] = lw; lmax_lo = fmaxf(lmax_lo, x);
            x = sc[nf][2] + bhi.x; lw = whi.x;
            if (d0 || lw <= 1e-5f) { x = -3.0e38f; lw = 0.f; }
            sc[nf][2] = x; pw[nf][2] = lw; lmax_hi = fmaxf(lmax_hi, x);
            x = sc[nf][3] + bhi.y; lw = whi.y;
            if (d1 || lw <= 1e-5f) { x = -3.0e38f; lw = 0.f; }
            sc[nf][3] = x; pw[nf][3] = lw; lmax_hi = fmaxf(lmax_hi, x);
        }
#pragma unroll
        for (int o = 1; o < 4; o <<= 1) {
            lmax_lo = fmaxf(lmax_lo, __shfl_xor_sync(0xffffffffu, lmax_lo, o));
            lmax_hi = fmaxf(lmax_hi, __shfl_xor_sync(0xffffffffu, lmax_hi, o));
        }
        float nm_lo = fmaxf(m_lo, lmax_lo), nm_hi = fmaxf(m_hi, lmax_hi);
        float sl_lo = __expf(m_lo - nm_lo),  sl_hi = __expf(m_hi - nm_hi);
        m_lo = nm_lo; m_hi = nm_hi;

        float es_lo = 0.f, es_hi = 0.f;
#pragma unroll
        for (int nf = 0; nf < 4; nf++) {
            float e0 = __expf(sc[nf][0] - nm_lo); es_lo += e0;
            float e1 = __expf(sc[nf][1] - nm_lo); es_lo += e1;
            float e2 = __expf(sc[nf][2] - nm_hi); es_hi += e2;
            float e3 = __expf(sc[nf][3] - nm_hi); es_hi += e3;
            float p0 = e0 * pw[nf][0], p1 = e1 * pw[nf][1];
            float p2 = e2 * pw[nf][2], p3 = e3 * pw[nf][3];
            unsigned h0 = f2tf(p0), h1 = f2tf(p1), h2 = f2tf(p2), h3 = f2tf(p3);
            int pc = nf * 8 + 2 * tig;
            *(uint2*)&Ph[rlo * SPst + pc] = make_uint2(h0, h1);
            *(uint2*)&Ph[rhi * SPst + pc] = make_uint2(h2, h3);
            *(uint2*)&Pl[rlo * SPst + pc] = make_uint2(
                f2tf(p0 - __uint_as_float(h0)), f2tf(p1 - __uint_as_float(h1)));
            *(uint2*)&Pl[rhi * SPst + pc] = make_uint2(
                f2tf(p2 - __uint_as_float(h2)), f2tf(p3 - __uint_as_float(h3)));
        }
#pragma unroll
        for (int o = 1; o < 4; o <<= 1) {
            es_lo += __shfl_xor_sync(0xffffffffu, es_lo, o);
            es_hi += __shfl_xor_sync(0xffffffffu, es_hi, o);
        }
        l_lo = l_lo * sl_lo + es_lo;
        l_hi = l_hi * sl_hi + es_hi;
#pragma unroll
        for (int nf = 0; nf < NFV; nf++) {
            acc[nf][0] *= sl_lo; acc[nf][1] *= sl_lo;
            acc[nf][2] *= sl_hi; acc[nf][3] *= sl_hi;
        }
        __syncwarp();                          // P rows are warp-private

        // ---- PV: acc[16x96] += P[16x32] * V[32x96], 3xTF32
        const unsigned* Phu = (const unsigned*)Ph;
        const unsigned* Plu = (const unsigned*)Pl;
#pragma unroll
        for (int ks = 0; ks < 4; ks++) {
            int pc = ks * 8 + tig;
            unsigned ah0 = Phu[rlo * SPst + pc],     ah1 = Phu[rhi * SPst + pc];
            unsigned ah2 = Phu[rlo * SPst + pc + 4], ah3 = Phu[rhi * SPst + pc + 4];
            unsigned al0 = Plu[rlo * SPst + pc],     al1 = Plu[rhi * SPst + pc];
            unsigned al2 = Plu[rlo * SPst + pc + 4], al3 = Plu[rhi * SPst + pc + 4];
#pragma unroll
            for (int nf = 0; nf < NFV; nf++) {
                uint2 b0 = sV2[(ks * 8 + tig)     * 100 + nf * 8 + gid];
                uint2 b1 = sV2[(ks * 8 + tig + 4) * 100 + nf * 8 + gid];
                mma_tf32(acc[nf], ah0, ah1, ah2, ah3, b0.x, b1.x);
                mma_tf32(acc[nf], al0, al1, al2, al3, b0.x, b1.x);
                mma_tf32(acc[nf], ah0, ah1, ah2, ah3, b0.y, b1.y);
            }
        }
        __syncwarp();                          // next-iter P writes vs reads
    }

    float rl_lo = (l_lo > 0.f) ? 1.f / l_lo : 0.f;
    float rl_hi = (l_hi > 0.f) ? 1.f / l_hi : 0.f;
#pragma unroll
    for (int nf = 0; nf < NFV; nf++) {
        int d = nf * 8 + 2 * tig;
        int p = d >> 5, j = d & 31;
        *(float2*)&g_attn[((b * Tq + tlo) * Pq + p) * HIDq + h * 32 + j] =
            make_float2(acc[nf][0] * rl_lo, acc[nf][1] * rl_lo);
        *(float2*)&g_attn[((b * Tq + thi) * Pq + p) * HIDq + h * 32 + j] =
            make_float2(acc[nf][2] * rl_hi, acc[nf][3] * rl_hi);
    }
}

// ---------------------------------------------------------------------------
__global__ __launch_bounds__(128) void inv_kernel()
{
    const int bt = blockIdx.x;
    const float* a = &g_attn[bt * Pq * HIDq];
    const int tid = threadIdx.x;
    float s = 0.f;
    for (int i = tid; i < Pq * HIDq; i += 128) { float x = a[i]; s = fmaf(x, x, s); }
#pragma unroll
    for (int o = 16; o; o >>= 1) s += __shfl_xor_sync(0xffffffffu, s, o);
    __shared__ float ws[4];
    if ((tid & 31) == 0) ws[tid >> 5] = s;
    __syncthreads();
    if (tid == 0) {
        float tot = ws[0] + ws[1] + ws[2] + ws[3];
        g_inv[bt] = rsqrtf(tot * (1.0f / (float)HIDq) + 1e-3f);
    }
}

// ---------------------------------------------------------------------------
__global__ __launch_bounds__(256) void proj_kernel(
    const float* __restrict__ W, const float* __restrict__ lnw,
    float* __restrict__ out)
{
    __shared__ float Xs[16][64 + 4];
    __shared__ float Ws[16][64 + 4];
    const int bm = blockIdx.x, bn = blockIdx.y;
    const int tid = threadIdx.x;
    const int tx = tid & 15, ty = tid >> 4;
    const int lm = tid >> 2;
    const int lk = (tid & 3) << 2;
    const int row = bm * 64 + lm;
    const float invv = g_inv[row / 3];

    float acc[4][4];
#pragma unroll
    for (int i = 0; i < 4; i++)
#pragma unroll
        for (int j = 0; j < 4; j++) acc[i][j] = 0.f;

    for (int k0 = 0; k0 < HIDq; k0 += 16) {
        float4 xv = *(const float4*)&g_attn[row * HIDq + k0 + lk];
        float4 lw = *(const float4*)&lnw[k0 + lk];
        Xs[lk + 0][lm] = xv.x * lw.x * invv;
        Xs[lk + 1][lm] = xv.y * lw.y * invv;
        Xs[lk + 2][lm] = xv.z * lw.z * invv;
        Xs[lk + 3][lm] = xv.w * lw.w * invv;
        float4 wv = *(const float4*)&W[(bn * 64 + lm) * HIDq + k0 + lk];
        Ws[lk + 0][lm] = wv.x;
        Ws[lk + 1][lm] = wv.y;
        Ws[lk + 2][lm] = wv.z;
        Ws[lk + 3][lm] = wv.w;
        __syncthreads();
#pragma unroll
        for (int kk = 0; kk < 16; kk++) {
            float rm[4], rn[4];
#pragma unroll
            for (int i = 0; i < 4; i++) rm[i] = Xs[kk][ty * 4 + i];
#pragma unroll
            for (int j = 0; j < 4; j++) rn[j] = Ws[kk][tx * 4 + j];
#pragma unroll
            for (int i = 0; i < 4; i++)
#pragma unroll
                for (int j = 0; j < 4; j++)
                    acc[i][j] = fmaf(rm[i], rn[j], acc[i][j]);
        }
        __syncthreads();
    }
#pragma unroll
    for (int i = 0; i < 4; i++) {
        int r = bm * 64 + ty * 4 + i;
        *(float4*)&out[r * HIDq + bn * 64 + tx * 4] =
            make_float4(acc[i][0], acc[i][1], acc[i][2], acc[i][3]);
    }
}

// ---------------------------------------------------------------------------
extern "C" void kernel_launch(void* const* d_in, const int* in_sizes, int n_in,
                              void* d_out, int out_size)
{
    const float* q    = (const float*)d_in[0];
    const float* k    = (const float*)d_in[1];
    const float* v    = (const float*)d_in[2];
    const float* bias = (const float*)d_in[3];
    const unsigned char* kpm   = (const unsigned char*)d_in[4];
    const int*   outcell       = (const int*)d_in[5];
    const float* law  = (const float*)d_in[6];
    const unsigned char* emask = (const unsigned char*)d_in[7];
    const float* W    = (const float*)d_in[8];
    const float* lnw  = (const float*)d_in[9];
    float* out = (float*)d_out;

    cudaFuncSetAttribute(attn_kernel,
        cudaFuncAttributeMaxDynamicSharedMemorySize, SMEMSZ);

    int units = Bq * Tq * Hq * 36;
    presplit_kernel<<<(units + 255) / 256, 256>>>(k, v);

    dim3 g1(Tq / TT, Hq, Bq);
    attn_kernel<<<g1, 128, SMEMSZ>>>(q, bias, kpm, outcell, law, emask);
    inv_kernel<<<Bq * Tq, 128>>>();
    dim3 g3((Bq * Tq * Pq) / 64, HIDq / 64);
    proj_kernel<<<g3, 256>>>(W, lnw, out);
}

// round 5
// speedup vs baseline: 2.5656x; 1.0832x over previous
#include <cuda_runtime.h>
#include <math.h>

#define Bq   4
#define Tq   512
#define Pq   3
#define HIDq 512
#define Hq   16
#define EXPq 512
#define Sq   1024
#define Dq   96

#define TT   128     // t rows per block (8 warps x 16)
#define TS   32      // s cols per tile
#define KSN  12      // Dq/8 k-steps for QK
#define NFV  12      // Dq/8 n-frags for PV
#define SPst 36      // P smem row stride (floats)

// ---- attn dynamic smem layout (bytes), double-buffered K/V ----
#define A_OFF_K0 0         // uint4 [32 cols][52] : 26,624 per buf
#define A_OFF_V0 53248     // uint2 [32 rows][100]: 25,600 per buf
#define A_OFF_PH 104448    // float [128][36] : 18,432
#define A_OFF_PL 122880    // float [128][36] : 18,432
#define A_OFF_DD 141312    // uchar [2][32]
#define A_SMEM   141440

// ---- proj dynamic smem layout: X/W tiles, double-buffered ----
#define P_STR    36        // uint4 row stride (bank-conflict-free)
#define P_OFF_X0 0         // uint4 [64][36]  : 36,864 per buf
#define P_OFF_W0 73728     // uint4 [128][36] : 73,728 per buf
#define P_SMEM   221184

// Pre-split storage (fragment-native):
// g_K[(b*T+t)*H+h]: 48 uint4 (ks*4+tig) = (hi(d),hi(d+4),lo(d),lo(d+4)), d=8ks+tig
// g_V[(b*T+t)*H+h]: 96 uint2 (hi,lo)
// g_Xs[m]: 256 uint4 (ks*4+tig) for X[m][k]=attn*lnw*inv, m=(b*T+t)*3+p
// g_Ws[n]: 256 uint4 for W[n][k]
__device__ uint4 g_K[Bq * Tq * Hq * 48];
__device__ uint2 g_V[Bq * Tq * Hq * 96];
__device__ float g_attn[Bq * Tq * Pq * HIDq];
__device__ uint4 g_Xs[Bq * Tq * Pq * 256];
__device__ uint4 g_Ws[HIDq * 256];

__device__ __forceinline__ unsigned f2tf(float f) {
    unsigned u; asm("cvt.rna.tf32.f32 %0,%1;" : "=r"(u) : "f"(f)); return u;
}
__device__ __forceinline__ void mma_tf32(float* c,
    unsigned a0, unsigned a1, unsigned a2, unsigned a3,
    unsigned b0, unsigned b1)
{
    asm volatile(
        "mma.sync.aligned.m16n8k8.row.col.f32.tf32.tf32.f32 "
        "{%0,%1,%2,%3},{%4,%5,%6,%7},{%8,%9},{%0,%1,%2,%3};"
        : "+f"(c[0]), "+f"(c[1]), "+f"(c[2]), "+f"(c[3])
        : "r"(a0), "r"(a1), "r"(a2), "r"(a3), "r"(b0), "r"(b1));
}
__device__ __forceinline__ void cpa16(unsigned dst, const void* src) {
    asm volatile("cp.async.cg.shared.global [%0], [%1], 16;\n" :: "r"(dst), "l"(src));
}
__device__ __forceinline__ void cpa_commit() {
    asm volatile("cp.async.commit_group;\n" ::: "memory");
}
__device__ __forceinline__ void cpa_wait1() {
    asm volatile("cp.async.wait_group 1;\n" ::: "memory");
}
__device__ __forceinline__ void cpa_wait0() {
    asm volatile("cp.async.wait_group 0;\n" ::: "memory");
}

// ---------------------------------------------------------------------------
// One-time K/V tf32 hi/lo split + head-gather transpose.
// ---------------------------------------------------------------------------
__global__ __launch_bounds__(256) void presplit_kernel(
    const float* __restrict__ k, const float* __restrict__ v)
{
    int gidx = blockIdx.x * 256 + threadIdx.x;
    const int U = 36;
    if (gidx >= Bq * Tq * Hq * U) return;
    int u = gidx % U;
    int bth = gidx / U;
    int h = bth % Hq;
    int bt = bth / Hq;

    if (u < 12) {
        int ks = u, d = ks * 8;
        const float* src = &k[(bt * Pq + (d >> 5)) * HIDq + h * 32 + (d & 31)];
        float4 x0 = *(const float4*)src;
        float4 x1 = *(const float4*)(src + 4);
        float e[8] = {x0.x, x0.y, x0.z, x0.w, x1.x, x1.y, x1.z, x1.w};
        uint4* dst = &g_K[bth * 48 + ks * 4];
#pragma unroll
        for (int tg = 0; tg < 4; tg++) {
            unsigned h0 = f2tf(e[tg]),     h1 = f2tf(e[tg + 4]);
            unsigned l0 = f2tf(e[tg]     - __uint_as_float(h0));
            unsigned l1 = f2tf(e[tg + 4] - __uint_as_float(h1));
            dst[tg] = make_uint4(h0, h1, l0, l1);
        }
    } else {
        int d = (u - 12) * 4;
        float4 x = *(const float4*)&v[(bt * Pq + (d >> 5)) * HIDq + h * 32 + (d & 31)];
        float e[4] = {x.x, x.y, x.z, x.w};
        uint2* dst = &g_V[bth * 96 + d];
#pragma unroll
        for (int t2 = 0; t2 < 4; t2++) {
            unsigned hh = f2tf(e[t2]);
            dst[t2] = make_uint2(hh, f2tf(e[t2] - __uint_as_float(hh)));
        }
    }
}

// ---------------------------------------------------------------------------
// One-time W tf32 hi/lo split into fragment-native rows.
// ---------------------------------------------------------------------------
__global__ __launch_bounds__(256) void presplit_w_kernel(const float* __restrict__ W)
{
    int g = blockIdx.x * 256 + threadIdx.x;
    if (g >= HIDq * 64) return;
    int n = g >> 6, ks = g & 63;
    const float* src = &W[n * HIDq + ks * 8];
    float4 x0 = *(const float4*)src;
    float4 x1 = *(const float4*)(src + 4);
    float e[8] = {x0.x, x0.y, x0.z, x0.w, x1.x, x1.y, x1.z, x1.w};
    uint4* dst = &g_Ws[n * 256 + ks * 4];
#pragma unroll
    for (int tg = 0; tg < 4; tg++) {
        unsigned h0 = f2tf(e[tg]),     h1 = f2tf(e[tg + 4]);
        unsigned l0 = f2tf(e[tg]     - __uint_as_float(h0));
        unsigned l1 = f2tf(e[tg + 4] - __uint_as_float(h1));
        dst[tg] = make_uint4(h0, h1, l0, l1);
    }
}

// ---------------------------------------------------------------------------
// Fused gather + flash attention, 3xTF32, double-buffered cp.async pipeline.
// Block = (b, h, 128-row t tile), 256 threads / 8 warps; warp owns 16 rows.
// ---------------------------------------------------------------------------
__global__ __launch_bounds__(256, 1) void attn_kernel(
    const float* __restrict__ q, const float* __restrict__ bias,
    const unsigned char* __restrict__ kpm, const int* __restrict__ outcell,
    const float* __restrict__ law, const unsigned char* __restrict__ emask)
{
    extern __shared__ __align__(16) char smembuf[];
    float*         Ph    = (float*)(smembuf + A_OFF_PH);
    float*         Pl    = (float*)(smembuf + A_OFF_PL);
    unsigned char* sDead = (unsigned char*)(smembuf + A_OFF_DD);
    unsigned sbase;
    { unsigned long long p0 = __cvta_generic_to_shared(smembuf); sbase = (unsigned)p0; }

    const int b  = blockIdx.z, h = blockIdx.y;
    const int t0 = blockIdx.x * TT;
    const int tid  = threadIdx.x;
    const int warp = tid >> 5, lane = tid & 31;
    const int gid  = lane >> 2, tig = lane & 3;
    const int rowBase = warp * 16;
    const int rlo = rowBase + gid, rhi = rlo + 8;
    const int tlo = t0 + rlo,      thi = t0 + rhi;

    // Preload Q A-fragments (hi/lo) into registers (reused across all 32 tiles)
    unsigned qh[KSN][4], ql[KSN][4];
#pragma unroll
    for (int ks = 0; ks < KSN; ks++) {
        int d0 = ks * 8 + tig, d1 = d0 + 4;
        float q00 = q[((b * Tq + tlo) * Pq + (d0 >> 5)) * HIDq + h * 32 + (d0 & 31)];
        float q10 = q[((b * Tq + thi) * Pq + (d0 >> 5)) * HIDq + h * 32 + (d0 & 31)];
        float q01 = q[((b * Tq + tlo) * Pq + (d1 >> 5)) * HIDq + h * 32 + (d1 & 31)];
        float q11 = q[((b * Tq + thi) * Pq + (d1 >> 5)) * HIDq + h * 32 + (d1 & 31)];
        qh[ks][0] = f2tf(q00); ql[ks][0] = f2tf(q00 - __uint_as_float(qh[ks][0]));
        qh[ks][1] = f2tf(q10); ql[ks][1] = f2tf(q10 - __uint_as_float(qh[ks][1]));
        qh[ks][2] = f2tf(q01); ql[ks][2] = f2tf(q01 - __uint_as_float(qh[ks][2]));
        qh[ks][3] = f2tf(q11); ql[ks][3] = f2tf(q11 - __uint_as_float(qh[ks][3]));
    }

    float m_lo = -3.0e38f, m_hi = -3.0e38f, l_lo = 0.f, l_hi = 0.f;
    float acc[NFV][4];
#pragma unroll
    for (int nf = 0; nf < NFV; nf++)
#pragma unroll
        for (int i = 0; i < 4; i++) acc[nf][i] = 0.f;

    // Issue gather loads for tile 'it' into buffer nb (no waits here).
    auto issue_tile = [&](int it, int nb) {
        int s0t = it * TS;
        unsigned kb = sbase + A_OFF_K0 + nb * 26624;
        unsigned vb = sbase + A_OFF_V0 + nb * 25600;
        for (int i = tid; i < 1536; i += 256) {
            int c = i / 48, f = i - c * 48;
            int s = s0t + c;
            int ts = (s < Tq) ? s : outcell[b * EXPq + (s - Tq)];
            int src = ((b * Tq + ts) * Hq + h);
            cpa16(kb + c * 832 + f * 16, &g_K[src * 48 + f]);
            cpa16(vb + c * 800 + f * 16, (const char*)&g_V[src * 96] + f * 16);
        }
        if (tid < TS) {
            int s = s0t + tid;
            sDead[nb * 32 + tid] =
                (s < Tq) ? kpm[b * Tq + s] : emask[b * EXPq + (s - Tq)];
        }
    };

    issue_tile(0, 0);
    cpa_commit();

    for (int it = 0; it < Sq / TS; it++) {
        const int cur = it & 1;
        if (it + 1 < Sq / TS) { issue_tile(it + 1, cur ^ 1); cpa_commit(); cpa_wait1(); }
        else                  { cpa_wait0(); }
        __syncthreads();

        const uint4* sK4 = (const uint4*)(smembuf + A_OFF_K0 + cur * 26624);
        const uint2* sV2 = (const uint2*)(smembuf + A_OFF_V0 + cur * 25600);
        const int s0 = it * TS;

        // ---- scores: C[16x32] per warp, 3xTF32
        float sc[4][4];
#pragma unroll
        for (int nf = 0; nf < 4; nf++)
#pragma unroll
            for (int i = 0; i < 4; i++) sc[nf][i] = 0.f;
#pragma unroll
        for (int ks = 0; ks < KSN; ks++) {
#pragma unroll
            for (int nf = 0; nf < 4; nf++) {
                uint4 bb = sK4[(nf * 8 + gid) * 52 + ks * 4 + tig];
                mma_tf32(sc[nf], qh[ks][0], qh[ks][1], qh[ks][2], qh[ks][3], bb.x, bb.y);
                mma_tf32(sc[nf], ql[ks][0], ql[ks][1], ql[ks][2], ql[ks][3], bb.x, bb.y);
                mma_tf32(sc[nf], qh[ks][0], qh[ks][1], qh[ks][2], qh[ks][3], bb.z, bb.w);
            }
        }

        // ---- bias + masks + online softmax (warp-local)
        float pw[4][4];
        float lmax_lo = -3.0e38f, lmax_hi = -3.0e38f;
#pragma unroll
        for (int nf = 0; nf < 4; nf++) {
            int colL = nf * 8 + 2 * tig;
            int col  = s0 + colL;
            float2 blo = *(const float2*)&bias[((b * Hq + h) * Tq + tlo) * Sq + col];
            float2 bhi = *(const float2*)&bias[((b * Hq + h) * Tq + thi) * Sq + col];
            float2 wlo = *(const float2*)&law [(b * Tq + tlo) * Sq + col];
            float2 whi = *(const float2*)&law [(b * Tq + thi) * Sq + col];
            unsigned char d0 = sDead[cur * 32 + colL], d1 = sDead[cur * 32 + colL + 1];

            float x, lw;
            x = sc[nf][0] + blo.x; lw = wlo.x;
            if (d0 || lw <= 1e-5f) { x = -3.0e38f; lw = 0.f; }
            sc[nf][0] = x; pw[nf][0] = lw; lmax_lo = fmaxf(lmax_lo, x);
            x = sc[nf][1] + blo.y; lw = wlo.y;
            if (d1 || lw <= 1e-5f) { x = -3.0e38f; lw = 0.f; }
            sc[nf][1] = x; pw[nf][1] = lw; lmax_lo = fmaxf(lmax_lo, x);
            x = sc[nf][2] + bhi.x; lw = whi.x;
            if (d0 || lw <= 1e-5f) { x = -3.0e38f; lw = 0.f; }
            sc[nf][2] = x; pw[nf][2] = lw; lmax_hi = fmaxf(lmax_hi, x);
            x = sc[nf][3] + bhi.y; lw = whi.y;
            if (d1 || lw <= 1e-5f) { x = -3.0e38f; lw = 0.f; }
            sc[nf][3] = x; pw[nf][3] = lw; lmax_hi = fmaxf(lmax_hi, x);
        }
#pragma unroll
        for (int o = 1; o < 4; o <<= 1) {
            lmax_lo = fmaxf(lmax_lo, __shfl_xor_sync(0xffffffffu, lmax_lo, o));
            lmax_hi = fmaxf(lmax_hi, __shfl_xor_sync(0xffffffffu, lmax_hi, o));
        }
        float nm_lo = fmaxf(m_lo, lmax_lo), nm_hi = fmaxf(m_hi, lmax_hi);
        float sl_lo = __expf(m_lo - nm_lo),  sl_hi = __expf(m_hi - nm_hi);
        m_lo = nm_lo; m_hi = nm_hi;

        float es_lo = 0.f, es_hi = 0.f;
#pragma unroll
        for (int nf = 0; nf < 4; nf++) {
            float e0 = __expf(sc[nf][0] - nm_lo); es_lo += e0;
            float e1 = __expf(sc[nf][1] - nm_lo); es_lo += e1;
            float e2 = __expf(sc[nf][2] - nm_hi); es_hi += e2;
            float e3 = __expf(sc[nf][3] - nm_hi); es_hi += e3;
            float p0 = e0 * pw[nf][0], p1 = e1 * pw[nf][1];
            float p2 = e2 * pw[nf][2], p3 = e3 * pw[nf][3];
            unsigned h0 = f2tf(p0), h1 = f2tf(p1), h2 = f2tf(p2), h3 = f2tf(p3);
            int pc = nf * 8 + 2 * tig;
            *(uint2*)&Ph[rlo * SPst + pc] = make_uint2(h0, h1);
            *(uint2*)&Ph[rhi * SPst + pc] = make_uint2(h2, h3);
            *(uint2*)&Pl[rlo * SPst + pc] = make_uint2(
                f2tf(p0 - __uint_as_float(h0)), f2tf(p1 - __uint_as_float(h1)));
            *(uint2*)&Pl[rhi * SPst + pc] = make_uint2(
                f2tf(p2 - __uint_as_float(h2)), f2tf(p3 - __uint_as_float(h3)));
        }
#pragma unroll
        for (int o = 1; o < 4; o <<= 1) {
            es_lo += __shfl_xor_sync(0xffffffffu, es_lo, o);
            es_hi += __shfl_xor_sync(0xffffffffu, es_hi, o);
        }
        l_lo = l_lo * sl_lo + es_lo;
        l_hi = l_hi * sl_hi + es_hi;
#pragma unroll
        for (int nf = 0; nf < NFV; nf++) {
            acc[nf][0] *= sl_lo; acc[nf][1] *= sl_lo;
            acc[nf][2] *= sl_hi; acc[nf][3] *= sl_hi;
        }
        __syncwarp();                          // P rows are warp-private

        // ---- PV: acc[16x96] += P[16x32] * V[32x96], 3xTF32
        const unsigned* Phu = (const unsigned*)Ph;
        const unsigned* Plu = (const unsigned*)Pl;
#pragma unroll
        for (int ks = 0; ks < 4; ks++) {
            int pc = ks * 8 + tig;
            unsigned ah0 = Phu[rlo * SPst + pc],     ah1 = Phu[rhi * SPst + pc];
            unsigned ah2 = Phu[rlo * SPst + pc + 4], ah3 = Phu[rhi * SPst + pc + 4];
            unsigned al0 = Plu[rlo * SPst + pc],     al1 = Plu[rhi * SPst + pc];
            unsigned al2 = Plu[rlo * SPst + pc + 4], al3 = Plu[rhi * SPst + pc + 4];
#pragma unroll
            for (int nf = 0; nf < NFV; nf++) {
                uint2 b0 = sV2[(ks * 8 + tig)     * 100 + nf * 8 + gid];
                uint2 b1 = sV2[(ks * 8 + tig + 4) * 100 + nf * 8 + gid];
                mma_tf32(acc[nf], ah0, ah1, ah2, ah3, b0.x, b1.x);
                mma_tf32(acc[nf], al0, al1, al2, al3, b0.x, b1.x);
                mma_tf32(acc[nf], ah0, ah1, ah2, ah3, b0.y, b1.y);
            }
        }
        __syncthreads();                       // all reads of buf[cur] done
    }

    float rl_lo = (l_lo > 0.f) ? 1.f / l_lo : 0.f;
    float rl_hi = (l_hi > 0.f) ? 1.f / l_hi : 0.f;
#pragma unroll
    for (int nf = 0; nf < NFV; nf++) {
        int d = nf * 8 + 2 * tig;
        int p = d >> 5, j = d & 31;
        *(float2*)&g_attn[((b * Tq + tlo) * Pq + p) * HIDq + h * 32 + j] =
            make_float2(acc[nf][0] * rl_lo, acc[nf][1] * rl_lo);
        *(float2*)&g_attn[((b * Tq + thi) * Pq + p) * HIDq + h * 32 + j] =
            make_float2(acc[nf][2] * rl_hi, acc[nf][3] * rl_hi);
    }
}

// ---------------------------------------------------------------------------
// inv + scale + split: X = attn*lnw*inv, written hi/lo fragment-native.
// ---------------------------------------------------------------------------
__global__ __launch_bounds__(128) void inv_split_kernel(const float* __restrict__ lnw)
{
    const int bt = blockIdx.x;
    const float* a = &g_attn[bt * Pq * HIDq];
    const int tid = threadIdx.x;
    float s = 0.f;
    for (int i = tid; i < (Pq * HIDq) / 4; i += 128) {
        float4 x = *(const float4*)&a[i * 4];
        s = fmaf(x.x, x.x, s); s = fmaf(x.y, x.y, s);
        s = fmaf(x.z, x.z, s); s = fmaf(x.w, x.w, s);
    }
#pragma unroll
    for (int o = 16; o; o >>= 1) s += __shfl_xor_sync(0xffffffffu, s, o);
    __shared__ float ws[4];
    __shared__ float sInv;
    if ((tid & 31) == 0) ws[tid >> 5] = s;
    __syncthreads();
    if (tid == 0) {
        float tot = ws[0] + ws[1] + ws[2] + ws[3];
        sInv = rsqrtf(tot * (1.0f / (float)HIDq) + 1e-3f);
    }
    __syncthreads();
    const float inv = sInv;

    for (int u = tid; u < Pq * 256; u += 128) {      // 768 uint4 per (b,t)
        int p = u >> 8, j = u & 255;
        int ks = j >> 2, tg = j & 3;
        int k0 = ks * 8 + tg;
        float x0 = a[p * HIDq + k0]     * lnw[k0]     * inv;
        float x1 = a[p * HIDq + k0 + 4] * lnw[k0 + 4] * inv;
        unsigned h0 = f2tf(x0), h1 = f2tf(x1);
        g_Xs[(bt * Pq + p) * 256 + j] = make_uint4(
            h0, h1,
            f2tf(x0 - __uint_as_float(h0)), f2tf(x1 - __uint_as_float(h1)));
    }
}

// ---------------------------------------------------------------------------
// Projection GEMM: out[m][n] = sum_k X[m][k]*W[n][k], 3xTF32.
// Block = 256 thr / 8 warps; tile M=64 x N=128; K chunked by 64, double-buffered.
// ---------------------------------------------------------------------------
__global__ __launch_bounds__(256, 1) void proj_kernel(float* __restrict__ out)
{
    extern __shared__ __align__(16) char smembuf[];
    unsigned sbase;
    { unsigned long long p0 = __cvta_generic_to_shared(smembuf); sbase = (unsigned)p0; }

    const int bm = blockIdx.x, bn = blockIdx.y;
    const int tid  = threadIdx.x;
    const int warp = tid >> 5, lane = tid & 31;
    const int gid  = lane >> 2, tig = lane & 3;
    const int wm = warp & 3, wn = warp >> 2;

    auto load_chunk = [&](int c, int nb) {
        unsigned xb = sbase + P_OFF_X0 + nb * 36864;
        for (int i = tid; i < 2048; i += 256) {          // X: 64 rows x 32 u4
            int r = i >> 5, f = i & 31;
            cpa16(xb + (r * P_STR + f) * 16, &g_Xs[(bm * 64 + r) * 256 + c * 32 + f]);
        }
        unsigned wb = sbase + P_OFF_W0 + nb * 73728;
        for (int i = tid; i < 4096; i += 256) {          // W: 128 rows x 32 u4
            int r = i >> 5, f = i & 31;
            cpa16(wb + (r * P_STR + f) * 16, &g_Ws[(bn * 128 + r) * 256 + c * 32 + f]);
        }
    };

    float acc[8][4];
#pragma unroll
    for (int nf = 0; nf < 8; nf++)
#pragma unroll
        for (int i = 0; i < 4; i++) acc[nf][i] = 0.f;

    load_chunk(0, 0);
    cpa_commit();

    for (int c = 0; c < 8; c++) {
        const int cur = c & 1;
        if (c + 1 < 8) { load_chunk(c + 1, cur ^ 1); cpa_commit(); cpa_wait1(); }
        else           { cpa_wait0(); }
        __syncthreads();

        const uint4* Xs = (const uint4*)(smembuf + P_OFF_X0 + cur * 36864);
        const uint4* Wt = (const uint4*)(smembuf + P_OFF_W0 + cur * 73728);
#pragma unroll
        for (int ks = 0; ks < 8; ks++) {
            uint4 aL = Xs[(wm * 16 + gid)     * P_STR + ks * 4 + tig];
            uint4 aH = Xs[(wm * 16 + gid + 8) * P_STR + ks * 4 + tig];
#pragma unroll
            for (int nf = 0; nf < 8; nf++) {
                uint4 w4 = Wt[(wn * 64 + nf * 8 + gid) * P_STR + ks * 4 + tig];
                mma_tf32(acc[nf], aL.x, aH.x, aL.y, aH.y, w4.x, w4.y);  // hi*hi
                mma_tf32(acc[nf], aL.z, aH.z, aL.w, aH.w, w4.x, w4.y);  // lo*hi
                mma_tf32(acc[nf], aL.x, aH.x, aL.y, aH.y, w4.z, w4.w);  // hi*lo
            }
        }
        __syncthreads();
    }

    const int mlo = bm * 64 + wm * 16 + gid;
    const int mhi = mlo + 8;
#pragma unroll
    for (int nf = 0; nf < 8; nf++) {
        int col = bn * 128 + wn * 64 + nf * 8 + 2 * tig;
        *(float2*)&out[mlo * HIDq + col] = make_float2(acc[nf][0], acc[nf][1]);
        *(float2*)&out[mhi * HIDq + col] = make_float2(acc[nf][2], acc[nf][3]);
    }
}

// ---------------------------------------------------------------------------
extern "C" void kernel_launch(void* const* d_in, const int* in_sizes, int n_in,
                              void* d_out, int out_size)
{
    const float* q    = (const float*)d_in[0];
    const float* k    = (const float*)d_in[1];
    const float* v    = (const float*)d_in[2];
    const float* bias = (const float*)d_in[3];
    const unsigned char* kpm   = (const unsigned char*)d_in[4];
    const int*   outcell       = (const int*)d_in[5];
    const float* law  = (const float*)d_in[6];
    const unsigned char* emask = (const unsigned char*)d_in[7];
    const float* W    = (const float*)d_in[8];
    const float* lnw  = (const float*)d_in[9];
    float* out = (float*)d_out;

    cudaFuncSetAttribute(attn_kernel,
        cudaFuncAttributeMaxDynamicSharedMemorySize, A_SMEM);
    cudaFuncSetAttribute(proj_kernel,
        cudaFuncAttributeMaxDynamicSharedMemorySize, P_SMEM);

    int units = Bq * Tq * Hq * 36;
    presplit_kernel<<<(units + 255) / 256, 256>>>(k, v);
    presplit_w_kernel<<<(HIDq * 64 + 255) / 256, 256>>>(W);

    dim3 g1(Tq / TT, Hq, Bq);
    attn_kernel<<<g1, 256, A_SMEM>>>(q, bias, kpm, outcell, law, emask);

    inv_split_kernel<<<Bq * Tq, 128>>>(lnw);

    dim3 g3((Bq * Tq * Pq) / 64, HIDq / 128);
    proj_kernel<<<g3, 256, P_SMEM>>>(out);
}

// round 6
// speedup vs baseline: 2.6302x; 1.0252x over previous
#include <cuda_runtime.h>
#include <math.h>

#define Bq   4
#define Tq   512
#define Pq   3
#define HIDq 512
#define Hq   16
#define EXPq 512
#define Sq   1024
#define Dq   96

#define TT   128     // t rows per block (8 warps x 16)
#define TS   32      // s cols per tile
#define KSN  12      // Dq/8 k-steps for QK
#define NFV  12      // Dq/8 n-frags for PV
#define SPst 36      // P smem row stride (floats)
#define BLst 36      // bias/law smem row stride (floats)

// ---- attn dynamic smem layout (bytes), double-buffered K/V/bias/law ----
#define A_OFF_K0 0         // uint4 [32 cols][52] : 26,624 per buf
#define A_OFF_V0 53248     // uint2 [32 rows][100]: 25,600 per buf
#define A_OFF_B0 104448    // float [128][36] : 18,432 per buf
#define A_OFF_L0 141312    // float [128][36] : 18,432 per buf
#define A_OFF_PH 178176    // float [128][36] : 18,432
#define A_OFF_PL 196608    // float [128][36] : 18,432
#define A_OFF_DD 215040    // uchar [2][32]
#define A_SMEM   215168

// ---- proj dynamic smem layout: X/W tiles, double-buffered ----
#define P_STR    36
#define P_OFF_X0 0         // uint4 [64][36]  : 36,864 per buf
#define P_OFF_W0 73728     // uint4 [128][36] : 73,728 per buf
#define P_SMEM   221184

// Pre-split storage (fragment-native):
__device__ uint4 g_K[Bq * Tq * Hq * 48];
__device__ uint2 g_V[Bq * Tq * Hq * 96];
__device__ float g_attn[Bq * Tq * Pq * HIDq];
__device__ uint4 g_Xs[Bq * Tq * Pq * 256];
__device__ uint4 g_Ws[HIDq * 256];

__device__ __forceinline__ unsigned f2tf(float f) {
    unsigned u; asm("cvt.rna.tf32.f32 %0,%1;" : "=r"(u) : "f"(f)); return u;
}
__device__ __forceinline__ void mma_tf32(float* c,
    unsigned a0, unsigned a1, unsigned a2, unsigned a3,
    unsigned b0, unsigned b1)
{
    asm volatile(
        "mma.sync.aligned.m16n8k8.row.col.f32.tf32.tf32.f32 "
        "{%0,%1,%2,%3},{%4,%5,%6,%7},{%8,%9},{%0,%1,%2,%3};"
        : "+f"(c[0]), "+f"(c[1]), "+f"(c[2]), "+f"(c[3])
        : "r"(a0), "r"(a1), "r"(a2), "r"(a3), "r"(b0), "r"(b1));
}
__device__ __forceinline__ void cpa16(unsigned dst, const void* src) {
    asm volatile("cp.async.cg.shared.global [%0], [%1], 16;\n" :: "r"(dst), "l"(src));
}
__device__ __forceinline__ void cpa_commit() {
    asm volatile("cp.async.commit_group;\n" ::: "memory");
}
__device__ __forceinline__ void cpa_wait1() {
    asm volatile("cp.async.wait_group 1;\n" ::: "memory");
}
__device__ __forceinline__ void cpa_wait0() {
    asm volatile("cp.async.wait_group 0;\n" ::: "memory");
}

// ---------------------------------------------------------------------------
// One-time K/V tf32 hi/lo split + head-gather transpose.
// ---------------------------------------------------------------------------
__global__ __launch_bounds__(256) void presplit_kernel(
    const float* __restrict__ k, const float* __restrict__ v)
{
    int gidx = blockIdx.x * 256 + threadIdx.x;
    const int U = 36;
    if (gidx >= Bq * Tq * Hq * U) return;
    int u = gidx % U;
    int bth = gidx / U;
    int h = bth % Hq;
    int bt = bth / Hq;

    if (u < 12) {
        int ks = u, d = ks * 8;
        const float* src = &k[(bt * Pq + (d >> 5)) * HIDq + h * 32 + (d & 31)];
        float4 x0 = *(const float4*)src;
        float4 x1 = *(const float4*)(src + 4);
        float e[8] = {x0.x, x0.y, x0.z, x0.w, x1.x, x1.y, x1.z, x1.w};
        uint4* dst = &g_K[bth * 48 + ks * 4];
#pragma unroll
        for (int tg = 0; tg < 4; tg++) {
            unsigned h0 = f2tf(e[tg]),     h1 = f2tf(e[tg + 4]);
            unsigned l0 = f2tf(e[tg]     - __uint_as_float(h0));
            unsigned l1 = f2tf(e[tg + 4] - __uint_as_float(h1));
            dst[tg] = make_uint4(h0, h1, l0, l1);
        }
    } else {
        int d = (u - 12) * 4;
        float4 x = *(const float4*)&v[(bt * Pq + (d >> 5)) * HIDq + h * 32 + (d & 31)];
        float e[4] = {x.x, x.y, x.z, x.w};
        uint2* dst = &g_V[bth * 96 + d];
#pragma unroll
        for (int t2 = 0; t2 < 4; t2++) {
            unsigned hh = f2tf(e[t2]);
            dst[t2] = make_uint2(hh, f2tf(e[t2] - __uint_as_float(hh)));
        }
    }
}

// ---------------------------------------------------------------------------
// One-time W tf32 hi/lo split into fragment-native rows.
// ---------------------------------------------------------------------------
__global__ __launch_bounds__(256) void presplit_w_kernel(const float* __restrict__ W)
{
    int g = blockIdx.x * 256 + threadIdx.x;
    if (g >= HIDq * 64) return;
    int n = g >> 6, ks = g & 63;
    const float* src = &W[n * HIDq + ks * 8];
    float4 x0 = *(const float4*)src;
    float4 x1 = *(const float4*)(src + 4);
    float e[8] = {x0.x, x0.y, x0.z, x0.w, x1.x, x1.y, x1.z, x1.w};
    uint4* dst = &g_Ws[n * 256 + ks * 4];
#pragma unroll
    for (int tg = 0; tg < 4; tg++) {
        unsigned h0 = f2tf(e[tg]),     h1 = f2tf(e[tg + 4]);
        unsigned l0 = f2tf(e[tg]     - __uint_as_float(h0));
        unsigned l1 = f2tf(e[tg + 4] - __uint_as_float(h1));
        dst[tg] = make_uint4(h0, h1, l0, l1);
    }
}

// ---------------------------------------------------------------------------
// Fused gather + flash attention, 3xTF32, double-buffered cp.async pipeline
// for K, V, bias AND law (softmax phase is LDS-only).
// ---------------------------------------------------------------------------
__global__ __launch_bounds__(256, 1) void attn_kernel(
    const float* __restrict__ q, const float* __restrict__ bias,
    const unsigned char* __restrict__ kpm, const int* __restrict__ outcell,
    const float* __restrict__ law, const unsigned char* __restrict__ emask)
{
    extern __shared__ __align__(16) char smembuf[];
    float*         Ph    = (float*)(smembuf + A_OFF_PH);
    float*         Pl    = (float*)(smembuf + A_OFF_PL);
    unsigned char* sDead = (unsigned char*)(smembuf + A_OFF_DD);
    unsigned sbase;
    { unsigned long long p0 = __cvta_generic_to_shared(smembuf); sbase = (unsigned)p0; }

    const int b  = blockIdx.z, h = blockIdx.y;
    const int t0 = blockIdx.x * TT;
    const int tid  = threadIdx.x;
    const int warp = tid >> 5, lane = tid & 31;
    const int gid  = lane >> 2, tig = lane & 3;
    const int rowBase = warp * 16;
    const int rlo = rowBase + gid, rhi = rlo + 8;
    const int tlo = t0 + rlo,      thi = t0 + rhi;

    // Preload Q A-fragments (hi/lo) into registers (reused across all 32 tiles)
    unsigned qh[KSN][4], ql[KSN][4];
#pragma unroll
    for (int ks = 0; ks < KSN; ks++) {
        int d0 = ks * 8 + tig, d1 = d0 + 4;
        float q00 = q[((b * Tq + tlo) * Pq + (d0 >> 5)) * HIDq + h * 32 + (d0 & 31)];
        float q10 = q[((b * Tq + thi) * Pq + (d0 >> 5)) * HIDq + h * 32 + (d0 & 31)];
        float q01 = q[((b * Tq + tlo) * Pq + (d1 >> 5)) * HIDq + h * 32 + (d1 & 31)];
        float q11 = q[((b * Tq + thi) * Pq + (d1 >> 5)) * HIDq + h * 32 + (d1 & 31)];
        qh[ks][0] = f2tf(q00); ql[ks][0] = f2tf(q00 - __uint_as_float(qh[ks][0]));
        qh[ks][1] = f2tf(q10); ql[ks][1] = f2tf(q10 - __uint_as_float(qh[ks][1]));
        qh[ks][2] = f2tf(q01); ql[ks][2] = f2tf(q01 - __uint_as_float(qh[ks][2]));
        qh[ks][3] = f2tf(q11); ql[ks][3] = f2tf(q11 - __uint_as_float(qh[ks][3]));
    }

    float m_lo = -3.0e38f, m_hi = -3.0e38f, l_lo = 0.f, l_hi = 0.f;
    float acc[NFV][4];
#pragma unroll
    for (int nf = 0; nf < NFV; nf++)
#pragma unroll
        for (int i = 0; i < 4; i++) acc[nf][i] = 0.f;

    // Issue all gather/stream loads for tile 'it' into buffer nb.
    auto issue_tile = [&](int it, int nb) {
        int s0t = it * TS;
        unsigned kb = sbase + A_OFF_K0 + nb * 26624;
        unsigned vb = sbase + A_OFF_V0 + nb * 25600;
        for (int i = tid; i < 1536; i += 256) {           // K + V fragment rows
            int c = i / 48, f = i - c * 48;
            int s = s0t + c;
            int ts = (s < Tq) ? s : outcell[b * EXPq + (s - Tq)];
            int src = ((b * Tq + ts) * Hq + h);
            cpa16(kb + c * 832 + f * 16, &g_K[src * 48 + f]);
            cpa16(vb + c * 800 + f * 16, (const char*)&g_V[src * 96] + f * 16);
        }
        unsigned bb = sbase + A_OFF_B0 + nb * 18432;
        unsigned lb = sbase + A_OFF_L0 + nb * 18432;
        const float* bsrc = &bias[((b * Hq + h) * Tq + t0) * Sq + s0t];
        const float* lsrc = &law [(b * Tq + t0) * Sq + s0t];
        for (int i = tid; i < 1024; i += 256) {           // 128 rows x 8 chunks
            int r = i >> 3, f = i & 7;
            cpa16(bb + r * (BLst * 4) + f * 16, bsrc + r * Sq + f * 4);
            cpa16(lb + r * (BLst * 4) + f * 16, lsrc + r * Sq + f * 4);
        }
        if (tid < TS) {
            int s = s0t + tid;
            sDead[nb * 32 + tid] =
                (s < Tq) ? kpm[b * Tq + s] : emask[b * EXPq + (s - Tq)];
        }
    };

    issue_tile(0, 0);
    cpa_commit();

    for (int it = 0; it < Sq / TS; it++) {
        const int cur = it & 1;
        if (it + 1 < Sq / TS) { issue_tile(it + 1, cur ^ 1); cpa_commit(); cpa_wait1(); }
        else                  { cpa_wait0(); }
        __syncthreads();

        const uint4* sK4 = (const uint4*)(smembuf + A_OFF_K0 + cur * 26624);
        const uint2* sV2 = (const uint2*)(smembuf + A_OFF_V0 + cur * 25600);
        const float* sB  = (const float*)(smembuf + A_OFF_B0 + cur * 18432);
        const float* sL  = (const float*)(smembuf + A_OFF_L0 + cur * 18432);

        // ---- scores: C[16x32] per warp, 3xTF32
        float sc[4][4];
#pragma unroll
        for (int nf = 0; nf < 4; nf++)
#pragma unroll
            for (int i = 0; i < 4; i++) sc[nf][i] = 0.f;
#pragma unroll
        for (int ks = 0; ks < KSN; ks++) {
#pragma unroll
            for (int nf = 0; nf < 4; nf++) {
                uint4 bb = sK4[(nf * 8 + gid) * 52 + ks * 4 + tig];
                mma_tf32(sc[nf], qh[ks][0], qh[ks][1], qh[ks][2], qh[ks][3], bb.x, bb.y);
                mma_tf32(sc[nf], ql[ks][0], ql[ks][1], ql[ks][2], ql[ks][3], bb.x, bb.y);
                mma_tf32(sc[nf], qh[ks][0], qh[ks][1], qh[ks][2], qh[ks][3], bb.z, bb.w);
            }
        }

        // ---- bias + masks + online softmax (LDS-only operands)
        float pw[4][4];
        float lmax_lo = -3.0e38f, lmax_hi = -3.0e38f;
#pragma unroll
        for (int nf = 0; nf < 4; nf++) {
            int colL = nf * 8 + 2 * tig;
            float2 blo = *(const float2*)&sB[rlo * BLst + colL];
            float2 bhi = *(const float2*)&sB[rhi * BLst + colL];
            float2 wlo = *(const float2*)&sL[rlo * BLst + colL];
            float2 whi = *(const float2*)&sL[rhi * BLst + colL];
            unsigned char d0 = sDead[cur * 32 + colL], d1 = sDead[cur * 32 + colL + 1];

            float x, lw;
            x = sc[nf][0] + blo.x; lw = wlo.x;
            if (d0 || lw <= 1e-5f) { x = -3.0e38f; lw = 0.f; }
            sc[nf][0] = x; pw[nf][0] = lw; lmax_lo = fmaxf(lmax_lo, x);
            x = sc[nf][1] + blo.y; lw = wlo.y;
            if (d1 || lw <= 1e-5f) { x = -3.0e38f; lw = 0.f; }
            sc[nf][1] = x; pw[nf][1] = lw; lmax_lo = fmaxf(lmax_lo, x);
            x = sc[nf][2] + bhi.x; lw = whi.x;
            if (d0 || lw <= 1e-5f) { x = -3.0e38f; lw = 0.f; }
            sc[nf][2] = x; pw[nf][2] = lw; lmax_hi = fmaxf(lmax_hi, x);
            x = sc[nf][3] + bhi.y; lw = whi.y;
            if (d1 || lw <= 1e-5f) { x = -3.0e38f; lw = 0.f; }
            sc[nf][3] = x; pw[nf][3] = lw; lmax_hi = fmaxf(lmax_hi, x);
        }
#pragma unroll
        for (int o = 1; o < 4; o <<= 1) {
            lmax_lo = fmaxf(lmax_lo, __shfl_xor_sync(0xffffffffu, lmax_lo, o));
            lmax_hi = fmaxf(lmax_hi, __shfl_xor_sync(0xffffffffu, lmax_hi, o));
        }
        float nm_lo = fmaxf(m_lo, lmax_lo), nm_hi = fmaxf(m_hi, lmax_hi);
        float sl_lo = __expf(m_lo - nm_lo),  sl_hi = __expf(m_hi - nm_hi);
        m_lo = nm_lo; m_hi = nm_hi;

        float es_lo = 0.f, es_hi = 0.f;
#pragma unroll
        for (int nf = 0; nf < 4; nf++) {
            float e0 = __expf(sc[nf][0] - nm_lo); es_lo += e0;
            float e1 = __expf(sc[nf][1] - nm_lo); es_lo += e1;
            float e2 = __expf(sc[nf][2] - nm_hi); es_hi += e2;
            float e3 = __expf(sc[nf][3] - nm_hi); es_hi += e3;
            float p0 = e0 * pw[nf][0], p1 = e1 * pw[nf][1];
            float p2 = e2 * pw[nf][2], p3 = e3 * pw[nf][3];
            unsigned h0 = f2tf(p0), h1 = f2tf(p1), h2 = f2tf(p2), h3 = f2tf(p3);
            int pc = nf * 8 + 2 * tig;
            *(uint2*)&Ph[rlo * SPst + pc] = make_uint2(h0, h1);
            *(uint2*)&Ph[rhi * SPst + pc] = make_uint2(h2, h3);
            *(uint2*)&Pl[rlo * SPst + pc] = make_uint2(
                f2tf(p0 - __uint_as_float(h0)), f2tf(p1 - __uint_as_float(h1)));
            *(uint2*)&Pl[rhi * SPst + pc] = make_uint2(
                f2tf(p2 - __uint_as_float(h2)), f2tf(p3 - __uint_as_float(h3)));
        }
#pragma unroll
        for (int o = 1; o < 4; o <<= 1) {
            es_lo += __shfl_xor_sync(0xffffffffu, es_lo, o);
            es_hi += __shfl_xor_sync(0xffffffffu, es_hi, o);
        }
        l_lo = l_lo * sl_lo + es_lo;
        l_hi = l_hi * sl_hi + es_hi;
#pragma unroll
        for (int nf = 0; nf < NFV; nf++) {
            acc[nf][0] *= sl_lo; acc[nf][1] *= sl_lo;
            acc[nf][2] *= sl_hi; acc[nf][3] *= sl_hi;
        }
        __syncwarp();                          // P rows are warp-private

        // ---- PV: acc[16x96] += P[16x32] * V[32x96], 3xTF32
        const unsigned* Phu = (const unsigned*)Ph;
        const unsigned* Plu = (const unsigned*)Pl;
#pragma unroll
        for (int ks = 0; ks < 4; ks++) {
            int pc = ks * 8 + tig;
            unsigned ah0 = Phu[rlo * SPst + pc],     ah1 = Phu[rhi * SPst + pc];
            unsigned ah2 = Phu[rlo * SPst + pc + 4], ah3 = Phu[rhi * SPst + pc + 4];
            unsigned al0 = Plu[rlo * SPst + pc],     al1 = Plu[rhi * SPst + pc];
            unsigned al2 = Plu[rlo * SPst + pc + 4], al3 = Plu[rhi * SPst + pc + 4];
#pragma unroll
            for (int nf = 0; nf < NFV; nf++) {
                uint2 b0 = sV2[(ks * 8 + tig)     * 100 + nf * 8 + gid];
                uint2 b1 = sV2[(ks * 8 + tig + 4) * 100 + nf * 8 + gid];
                mma_tf32(acc[nf], ah0, ah1, ah2, ah3, b0.x, b1.x);
                mma_tf32(acc[nf], al0, al1, al2, al3, b0.x, b1.x);
                mma_tf32(acc[nf], ah0, ah1, ah2, ah3, b0.y, b1.y);
            }
        }
        __syncthreads();                       // all reads of buf[cur] done
    }

    float rl_lo = (l_lo > 0.f) ? 1.f / l_lo : 0.f;
    float rl_hi = (l_hi > 0.f) ? 1.f / l_hi : 0.f;
#pragma unroll
    for (int nf = 0; nf < NFV; nf++) {
        int d = nf * 8 + 2 * tig;
        int p = d >> 5, j = d & 31;
        *(float2*)&g_attn[((b * Tq + tlo) * Pq + p) * HIDq + h * 32 + j] =
            make_float2(acc[nf][0] * rl_lo, acc[nf][1] * rl_lo);
        *(float2*)&g_attn[((b * Tq + thi) * Pq + p) * HIDq + h * 32 + j] =
            make_float2(acc[nf][2] * rl_hi, acc[nf][3] * rl_hi);
    }
}

// ---------------------------------------------------------------------------
// inv + scale + split: X = attn*lnw*inv, written hi/lo fragment-native.
// ---------------------------------------------------------------------------
__global__ __launch_bounds__(128) void inv_split_kernel(const float* __restrict__ lnw)
{
    const int bt = blockIdx.x;
    const float* a = &g_attn[bt * Pq * HIDq];
    const int tid = threadIdx.x;
    float s = 0.f;
    for (int i = tid; i < (Pq * HIDq) / 4; i += 128) {
        float4 x = *(const float4*)&a[i * 4];
        s = fmaf(x.x, x.x, s); s = fmaf(x.y, x.y, s);
        s = fmaf(x.z, x.z, s); s = fmaf(x.w, x.w, s);
    }
#pragma unroll
    for (int o = 16; o; o >>= 1) s += __shfl_xor_sync(0xffffffffu, s, o);
    __shared__ float ws[4];
    __shared__ float sInv;
    if ((tid & 31) == 0) ws[tid >> 5] = s;
    __syncthreads();
    if (tid == 0) {
        float tot = ws[0] + ws[1] + ws[2] + ws[3];
        sInv = rsqrtf(tot * (1.0f / (float)HIDq) + 1e-3f);
    }
    __syncthreads();
    const float inv = sInv;

    for (int u = tid; u < Pq * 256; u += 128) {
        int p = u >> 8, j = u & 255;
        int ks = j >> 2, tg = j & 3;
        int k0 = ks * 8 + tg;
        float x0 = a[p * HIDq + k0]     * lnw[k0]     * inv;
        float x1 = a[p * HIDq + k0 + 4] * lnw[k0 + 4] * inv;
        unsigned h0 = f2tf(x0), h1 = f2tf(x1);
        g_Xs[(bt * Pq + p) * 256 + j] = make_uint4(
            h0, h1,
            f2tf(x0 - __uint_as_float(h0)), f2tf(x1 - __uint_as_float(h1)));
    }
}

// ---------------------------------------------------------------------------
// Projection GEMM: out[m][n] = sum_k X[m][k]*W[n][k], 3xTF32.
// ---------------------------------------------------------------------------
__global__ __launch_bounds__(256, 1) void proj_kernel(float* __restrict__ out)
{
    extern __shared__ __align__(16) char smembuf[];
    unsigned sbase;
    { unsigned long long p0 = __cvta_generic_to_shared(smembuf); sbase = (unsigned)p0; }

    const int bm = blockIdx.x, bn = blockIdx.y;
    const int tid  = threadIdx.x;
    const int warp = tid >> 5, lane = tid & 31;
    const int gid  = lane >> 2, tig = lane & 3;
    const int wm = warp & 3, wn = warp >> 2;

    auto load_chunk = [&](int c, int nb) {
        unsigned xb = sbase + P_OFF_X0 + nb * 36864;
        for (int i = tid; i < 2048; i += 256) {
            int r = i >> 5, f = i & 31;
            cpa16(xb + (r * P_STR + f) * 16, &g_Xs[(bm * 64 + r) * 256 + c * 32 + f]);
        }
        unsigned wb = sbase + P_OFF_W0 + nb * 73728;
        for (int i = tid; i < 4096; i += 256) {
            int r = i >> 5, f = i & 31;
            cpa16(wb + (r * P_STR + f) * 16, &g_Ws[(bn * 128 + r) * 256 + c * 32 + f]);
        }
    };

    float acc[8][4];
#pragma unroll
    for (int nf = 0; nf < 8; nf++)
#pragma unroll
        for (int i = 0; i < 4; i++) acc[nf][i] = 0.f;

    load_chunk(0, 0);
    cpa_commit();

    for (int c = 0; c < 8; c++) {
        const int cur = c & 1;
        if (c + 1 < 8) { load_chunk(c + 1, cur ^ 1); cpa_commit(); cpa_wait1(); }
        else           { cpa_wait0(); }
        __syncthreads();

        const uint4* Xs = (const uint4*)(smembuf + P_OFF_X0 + cur * 36864);
        const uint4* Wt = (const uint4*)(smembuf + P_OFF_W0 + cur * 73728);
#pragma unroll
        for (int ks = 0; ks < 8; ks++) {
            uint4 aL = Xs[(wm * 16 + gid)     * P_STR + ks * 4 + tig];
            uint4 aH = Xs[(wm * 16 + gid + 8) * P_STR + ks * 4 + tig];
#pragma unroll
            for (int nf = 0; nf < 8; nf++) {
                uint4 w4 = Wt[(wn * 64 + nf * 8 + gid) * P_STR + ks * 4 + tig];
                mma_tf32(acc[nf], aL.x, aH.x, aL.y, aH.y, w4.x, w4.y);
                mma_tf32(acc[nf], aL.z, aH.z, aL.w, aH.w, w4.x, w4.y);
                mma_tf32(acc[nf], aL.x, aH.x, aL.y, aH.y, w4.z, w4.w);
            }
        }
        __syncthreads();
    }

    const int mlo = bm * 64 + wm * 16 + gid;
    const int mhi = mlo + 8;
#pragma unroll
    for (int nf = 0; nf < 8; nf++) {
        int col = bn * 128 + wn * 64 + nf * 8 + 2 * tig;
        *(float2*)&out[mlo * HIDq + col] = make_float2(acc[nf][0], acc[nf][1]);
        *(float2*)&out[mhi * HIDq + col] = make_float2(acc[nf][2], acc[nf][3]);
    }
}

// ---------------------------------------------------------------------------
extern "C" void kernel_launch(void* const* d_in, const int* in_sizes, int n_in,
                              void* d_out, int out_size)
{
    const float* q    = (const float*)d_in[0];
    const float* k    = (const float*)d_in[1];
    const float* v    = (const float*)d_in[2];
    const float* bias = (const float*)d_in[3];
    const unsigned char* kpm   = (const unsigned char*)d_in[4];
    const int*   outcell       = (const int*)d_in[5];
    const float* law  = (const float*)d_in[6];
    const unsigned char* emask = (const unsigned char*)d_in[7];
    const float* W    = (const float*)d_in[8];
    const float* lnw  = (const float*)d_in[9];
    float* out = (float*)d_out;

    cudaFuncSetAttribute(attn_kernel,
        cudaFuncAttributeMaxDynamicSharedMemorySize, A_SMEM);
    cudaFuncSetAttribute(proj_kernel,
        cudaFuncAttributeMaxDynamicSharedMemorySize, P_SMEM);

    int units = Bq * Tq * Hq * 36;
    presplit_kernel<<<(units + 255) / 256, 256>>>(k, v);
    presplit_w_kernel<<<(HIDq * 64 + 255) / 256, 256>>>(W);

    dim3 g1(Tq / TT, Hq, Bq);
    attn_kernel<<<g1, 256, A_SMEM>>>(q, bias, kpm, outcell, law, emask);

    inv_split_kernel<<<Bq * Tq, 128>>>(lnw);

    dim3 g3((Bq * Tq * Pq) / 64, HIDq / 128);
    proj_kernel<<<g3, 256, P_SMEM>>>(out);
}

// round 7
// speedup vs baseline: 3.0736x; 1.1686x over previous
#include <cuda_runtime.h>
#include <math.h>

#define Bq   4
#define Tq   512
#define Pq   3
#define HIDq 512
#define Hq   16
#define EXPq 512
#define Sq   1024
#define Dq   96

#define TT   128     // t rows per block (8 warps x 16)
#define TS   32      // s cols per tile
#define KS16 6       // Dq/16 k-steps for QK (bf16 k16)
#define NFV  12      // Dq/8 n-frags for PV
#define SPst 36      // P smem row stride (floats)
#define BLst 36      // bias/law smem row stride (floats)
#define KBst 28      // K smem row stride (uint4)

// ---- attn dynamic smem layout (bytes), double-buffered ----
#define A_OFF_K0 0         // uint4 [32 cols][28] : 14,336 per buf
#define A_OFF_V0 28672     // uint2 [32 rows][100]: 25,600 per buf
#define A_OFF_B0 79872     // float [128][36] : 18,432 per buf
#define A_OFF_L0 116736    // float [128][36] : 18,432 per buf
#define A_OFF_PH 153600    // float [128][36] : 18,432
#define A_OFF_PL 172032    // float [128][36] : 18,432
#define A_OFF_DD 190464    // uchar [2][32]
#define A_SMEM   190528

// ---- proj dynamic smem layout (bf16 k16): X/W tiles, double-buffered ----
#define P_STR    20        // uint4 row stride
#define P_OFF_X0 0         // uint4 [64][20]  : 20,480 per buf
#define P_OFF_W0 40960     // uint4 [128][20] : 40,960 per buf
#define P_SMEM   122880

// Pre-split storage:
// g_Kb[bth*24 + ks*4 + tig] = (b0h,b1h,b0l,b1l) bf16x2 frags, k-pair d=16ks+2tig
// g_V  [bth*96 + d]         = (hi,lo) tf32
// g_Xb[m*128 + ks*4 + tg]   = (h(d0,d0+1), h(d0+8,d0+9), l.., l..) bf16x2, d0=16ks+2tg
// g_Wb[n*128 + ...]           same layout
__device__ uint4 g_Kb[Bq * Tq * Hq * 24];
__device__ uint2 g_V [Bq * Tq * Hq * 96];
__device__ float g_attn[Bq * Tq * Pq * HIDq];
__device__ uint4 g_Xb[Bq * Tq * Pq * 128];
__device__ uint4 g_Wb[HIDq * 128];

__device__ __forceinline__ unsigned f2tf(float f) {
    unsigned u; asm("cvt.rna.tf32.f32 %0,%1;" : "=r"(u) : "f"(f)); return u;
}
__device__ __forceinline__ unsigned packbf(float lo, float hi) {
    unsigned d; asm("cvt.rn.bf16x2.f32 %0,%1,%2;" : "=r"(d) : "f"(hi), "f"(lo));
    return d;
}
// bf16 hi/lo split of a k-pair, packed as bf16x2 (lo 16 bits = even k).
__device__ __forceinline__ void splitpack(float x0, float x1, unsigned& h, unsigned& l) {
    h = packbf(x0, x1);
    float h0 = __uint_as_float(h << 16);
    float h1 = __uint_as_float(h & 0xffff0000u);
    l = packbf(x0 - h0, x1 - h1);
}
__device__ __forceinline__ void mma_tf32(float* c,
    unsigned a0, unsigned a1, unsigned a2, unsigned a3,
    unsigned b0, unsigned b1)
{
    asm volatile(
        "mma.sync.aligned.m16n8k8.row.col.f32.tf32.tf32.f32 "
        "{%0,%1,%2,%3},{%4,%5,%6,%7},{%8,%9},{%0,%1,%2,%3};"
        : "+f"(c[0]), "+f"(c[1]), "+f"(c[2]), "+f"(c[3])
        : "r"(a0), "r"(a1), "r"(a2), "r"(a3), "r"(b0), "r"(b1));
}
__device__ __forceinline__ void mma_bf16(float* c,
    unsigned a0, unsigned a1, unsigned a2, unsigned a3,
    unsigned b0, unsigned b1)
{
    asm volatile(
        "mma.sync.aligned.m16n8k16.row.col.f32.bf16.bf16.f32 "
        "{%0,%1,%2,%3},{%4,%5,%6,%7},{%8,%9},{%0,%1,%2,%3};"
        : "+f"(c[0]), "+f"(c[1]), "+f"(c[2]), "+f"(c[3])
        : "r"(a0), "r"(a1), "r"(a2), "r"(a3), "r"(b0), "r"(b1));
}
__device__ __forceinline__ void cpa16(unsigned dst, const void* src) {
    asm volatile("cp.async.cg.shared.global [%0], [%1], 16;\n" :: "r"(dst), "l"(src));
}
__device__ __forceinline__ void cpa_commit() {
    asm volatile("cp.async.commit_group;\n" ::: "memory");
}
__device__ __forceinline__ void cpa_wait1() {
    asm volatile("cp.async.wait_group 1;\n" ::: "memory");
}
__device__ __forceinline__ void cpa_wait0() {
    asm volatile("cp.async.wait_group 0;\n" ::: "memory");
}

// ---------------------------------------------------------------------------
// One-time presplit: K -> bf16 hi/lo k16 B-frags, V -> tf32 hi/lo.
// unit u<24: K frag uint4; u>=24: V 4-elem group.
// ---------------------------------------------------------------------------
__global__ __launch_bounds__(256) void presplit_kernel(
    const float* __restrict__ k, const float* __restrict__ v)
{
    int gidx = blockIdx.x * 256 + threadIdx.x;
    const int U = 48;
    if (gidx >= Bq * Tq * Hq * U) return;
    int u = gidx % U;
    int bth = gidx / U;
    int h = bth % Hq;
    int bt = bth / Hq;

    if (u < 24) {
        int ks = u >> 2, tg = u & 3;
        int d0 = ks * 16 + 2 * tg;
        const float* src = &k[(bt * Pq + (d0 >> 5)) * HIDq + h * 32 + (d0 & 31)];
        float2 e01 = *(const float2*)src;
        float2 e89 = *(const float2*)(src + 8);
        unsigned b0h, b0l, b1h, b1l;
        splitpack(e01.x, e01.y, b0h, b0l);
        splitpack(e89.x, e89.y, b1h, b1l);
        g_Kb[bth * 24 + u] = make_uint4(b0h, b1h, b0l, b1l);
    } else {
        int d = (u - 24) * 4;
        float4 x = *(const float4*)&v[(bt * Pq + (d >> 5)) * HIDq + h * 32 + (d & 31)];
        float e[4] = {x.x, x.y, x.z, x.w};
        uint2* dst = &g_V[bth * 96 + d];
#pragma unroll
        for (int t2 = 0; t2 < 4; t2++) {
            unsigned hh = f2tf(e[t2]);
            dst[t2] = make_uint2(hh, f2tf(e[t2] - __uint_as_float(hh)));
        }
    }
}

// ---------------------------------------------------------------------------
// One-time W bf16 hi/lo split into k16 fragment rows.
// ---------------------------------------------------------------------------
__global__ __launch_bounds__(256) void presplit_w_kernel(const float* __restrict__ W)
{
    int g = blockIdx.x * 256 + threadIdx.x;
    if (g >= HIDq * 128) return;
    int n = g >> 7, j = g & 127;
    int ks = j >> 2, tg = j & 3;
    int d0 = ks * 16 + 2 * tg;
    const float* src = &W[n * HIDq + d0];
    float2 e01 = *(const float2*)src;
    float2 e89 = *(const float2*)(src + 8);
    unsigned b0h, b0l, b1h, b1l;
    splitpack(e01.x, e01.y, b0h, b0l);
    splitpack(e89.x, e89.y, b1h, b1l);
    g_Wb[n * 128 + j] = make_uint4(b0h, b1h, b0l, b1l);
}

// ---------------------------------------------------------------------------
// Fused gather + flash attention: QK in 3xBF16 k16, PV in 3xTF32.
// ---------------------------------------------------------------------------
__global__ __launch_bounds__(256, 1) void attn_kernel(
    const float* __restrict__ q, const float* __restrict__ bias,
    const unsigned char* __restrict__ kpm, const int* __restrict__ outcell,
    const float* __restrict__ law, const unsigned char* __restrict__ emask)
{
    extern __shared__ __align__(16) char smembuf[];
    float*         Ph    = (float*)(smembuf + A_OFF_PH);
    float*         Pl    = (float*)(smembuf + A_OFF_PL);
    unsigned char* sDead = (unsigned char*)(smembuf + A_OFF_DD);
    unsigned sbase;
    { unsigned long long p0 = __cvta_generic_to_shared(smembuf); sbase = (unsigned)p0; }

    const int b  = blockIdx.z, h = blockIdx.y;
    const int t0 = blockIdx.x * TT;
    const int tid  = threadIdx.x;
    const int warp = tid >> 5, lane = tid & 31;
    const int gid  = lane >> 2, tig = lane & 3;
    const int rowBase = warp * 16;
    const int rlo = rowBase + gid, rhi = rlo + 8;
    const int tlo = t0 + rlo,      thi = t0 + rhi;

    // Preload Q A-fragments (bf16 hi/lo, k16) — 48 regs total.
    unsigned qh[KS16][4], ql[KS16][4];
#pragma unroll
    for (int ks = 0; ks < KS16; ks++) {
        int d0 = ks * 16 + 2 * tig;
        int baseL = ((b * Tq + tlo) * Pq + (d0 >> 5)) * HIDq + h * 32 + (d0 & 31);
        int baseH = ((b * Tq + thi) * Pq + (d0 >> 5)) * HIDq + h * 32 + (d0 & 31);
        float2 qa = *(const float2*)&q[baseL];
        float2 qb = *(const float2*)&q[baseH];
        float2 qc = *(const float2*)&q[baseL + 8];
        float2 qd = *(const float2*)&q[baseH + 8];
        splitpack(qa.x, qa.y, qh[ks][0], ql[ks][0]);
        splitpack(qb.x, qb.y, qh[ks][1], ql[ks][1]);
        splitpack(qc.x, qc.y, qh[ks][2], ql[ks][2]);
        splitpack(qd.x, qd.y, qh[ks][3], ql[ks][3]);
    }

    float m_lo = -3.0e38f, m_hi = -3.0e38f, l_lo = 0.f, l_hi = 0.f;
    float acc[NFV][4];
#pragma unroll
    for (int nf = 0; nf < NFV; nf++)
#pragma unroll
        for (int i = 0; i < 4; i++) acc[nf][i] = 0.f;

    auto issue_tile = [&](int it, int nb) {
        int s0t = it * TS;
        unsigned kb = sbase + A_OFF_K0 + nb * 14336;
        unsigned vb = sbase + A_OFF_V0 + nb * 25600;
        for (int i = tid; i < 768; i += 256) {            // K: 32 x 24 chunks
            int c = i / 24, f = i - c * 24;
            int s = s0t + c;
            int ts = (s < Tq) ? s : outcell[b * EXPq + (s - Tq)];
            cpa16(kb + c * 448 + f * 16, &g_Kb[((b * Tq + ts) * Hq + h) * 24 + f]);
        }
        for (int i = tid; i < 1536; i += 256) {           // V: 32 x 48 chunks
            int c = i / 48, f = i - c * 48;
            int s = s0t + c;
            int ts = (s < Tq) ? s : outcell[b * EXPq + (s - Tq)];
            cpa16(vb + c * 800 + f * 16,
                  (const char*)&g_V[((b * Tq + ts) * Hq + h) * 96] + f * 16);
        }
        unsigned bb = sbase + A_OFF_B0 + nb * 18432;
        unsigned lb = sbase + A_OFF_L0 + nb * 18432;
        const float* bsrc = &bias[((b * Hq + h) * Tq + t0) * Sq + s0t];
        const float* lsrc = &law [(b * Tq + t0) * Sq + s0t];
        for (int i = tid; i < 1024; i += 256) {
            int r = i >> 3, f = i & 7;
            cpa16(bb + r * (BLst * 4) + f * 16, bsrc + r * Sq + f * 4);
            cpa16(lb + r * (BLst * 4) + f * 16, lsrc + r * Sq + f * 4);
        }
        if (tid < TS) {
            int s = s0t + tid;
            sDead[nb * 32 + tid] =
                (s < Tq) ? kpm[b * Tq + s] : emask[b * EXPq + (s - Tq)];
        }
    };

    issue_tile(0, 0);
    cpa_commit();

    for (int it = 0; it < Sq / TS; it++) {
        const int cur = it & 1;
        if (it + 1 < Sq / TS) { issue_tile(it + 1, cur ^ 1); cpa_commit(); cpa_wait1(); }
        else                  { cpa_wait0(); }
        __syncthreads();

        const uint4* sKb = (const uint4*)(smembuf + A_OFF_K0 + cur * 14336);
        const uint2* sV2 = (const uint2*)(smembuf + A_OFF_V0 + cur * 25600);
        const float* sB  = (const float*)(smembuf + A_OFF_B0 + cur * 18432);
        const float* sL  = (const float*)(smembuf + A_OFF_L0 + cur * 18432);

        // ---- scores: C[16x32] per warp, 3xBF16 k16
        float sc[4][4];
#pragma unroll
        for (int nf = 0; nf < 4; nf++)
#pragma unroll
            for (int i = 0; i < 4; i++) sc[nf][i] = 0.f;
#pragma unroll
        for (int ks = 0; ks < KS16; ks++) {
#pragma unroll
            for (int nf = 0; nf < 4; nf++) {
                uint4 bb = sKb[(nf * 8 + gid) * KBst + ks * 4 + tig];
                mma_bf16(sc[nf], qh[ks][0], qh[ks][1], qh[ks][2], qh[ks][3], bb.x, bb.y);
                mma_bf16(sc[nf], ql[ks][0], ql[ks][1], ql[ks][2], ql[ks][3], bb.x, bb.y);
                mma_bf16(sc[nf], qh[ks][0], qh[ks][1], qh[ks][2], qh[ks][3], bb.z, bb.w);
            }
        }

        // ---- bias + masks + online softmax (LDS-only operands)
        float pw[4][4];
        float lmax_lo = -3.0e38f, lmax_hi = -3.0e38f;
#pragma unroll
        for (int nf = 0; nf < 4; nf++) {
            int colL = nf * 8 + 2 * tig;
            float2 blo = *(const float2*)&sB[rlo * BLst + colL];
            float2 bhi = *(const float2*)&sB[rhi * BLst + colL];
            float2 wlo = *(const float2*)&sL[rlo * BLst + colL];
            float2 whi = *(const float2*)&sL[rhi * BLst + colL];
            unsigned char d0 = sDead[cur * 32 + colL], d1 = sDead[cur * 32 + colL + 1];

            float x, lw;
            x = sc[nf][0] + blo.x; lw = wlo.x;
            if (d0 || lw <= 1e-5f) { x = -3.0e38f; lw = 0.f; }
            sc[nf][0] = x; pw[nf][0] = lw; lmax_lo = fmaxf(lmax_lo, x);
            x = sc[nf][1] + blo.y; lw = wlo.y;
            if (d1 || lw <= 1e-5f) { x = -3.0e38f; lw = 0.f; }
            sc[nf][1] = x; pw[nf][1] = lw; lmax_lo = fmaxf(lmax_lo, x);
            x = sc[nf][2] + bhi.x; lw = whi.x;
            if (d0 || lw <= 1e-5f) { x = -3.0e38f; lw = 0.f; }
            sc[nf][2] = x; pw[nf][2] = lw; lmax_hi = fmaxf(lmax_hi, x);
            x = sc[nf][3] + bhi.y; lw = whi.y;
            if (d1 || lw <= 1e-5f) { x = -3.0e38f; lw = 0.f; }
            sc[nf][3] = x; pw[nf][3] = lw; lmax_hi = fmaxf(lmax_hi, x);
        }
#pragma unroll
        for (int o = 1; o < 4; o <<= 1) {
            lmax_lo = fmaxf(lmax_lo, __shfl_xor_sync(0xffffffffu, lmax_lo, o));
            lmax_hi = fmaxf(lmax_hi, __shfl_xor_sync(0xffffffffu, lmax_hi, o));
        }
        float nm_lo = fmaxf(m_lo, lmax_lo), nm_hi = fmaxf(m_hi, lmax_hi);
        float sl_lo = __expf(m_lo - nm_lo),  sl_hi = __expf(m_hi - nm_hi);
        m_lo = nm_lo; m_hi = nm_hi;

        float es_lo = 0.f, es_hi = 0.f;
#pragma unroll
        for (int nf = 0; nf < 4; nf++) {
            float e0 = __expf(sc[nf][0] - nm_lo); es_lo += e0;
            float e1 = __expf(sc[nf][1] - nm_lo); es_lo += e1;
            float e2 = __expf(sc[nf][2] - nm_hi); es_hi += e2;
            float e3 = __expf(sc[nf][3] - nm_hi); es_hi += e3;
            float p0 = e0 * pw[nf][0], p1 = e1 * pw[nf][1];
            float p2 = e2 * pw[nf][2], p3 = e3 * pw[nf][3];
            unsigned h0 = f2tf(p0), h1 = f2tf(p1), h2 = f2tf(p2), h3 = f2tf(p3);
            int pc = nf * 8 + 2 * tig;
            *(uint2*)&Ph[rlo * SPst + pc] = make_uint2(h0, h1);
            *(uint2*)&Ph[rhi * SPst + pc] = make_uint2(h2, h3);
            *(uint2*)&Pl[rlo * SPst + pc] = make_uint2(
                f2tf(p0 - __uint_as_float(h0)), f2tf(p1 - __uint_as_float(h1)));
            *(uint2*)&Pl[rhi * SPst + pc] = make_uint2(
                f2tf(p2 - __uint_as_float(h2)), f2tf(p3 - __uint_as_float(h3)));
        }
#pragma unroll
        for (int o = 1; o < 4; o <<= 1) {
            es_lo += __shfl_xor_sync(0xffffffffu, es_lo, o);
            es_hi += __shfl_xor_sync(0xffffffffu, es_hi, o);
        }
        l_lo = l_lo * sl_lo + es_lo;
        l_hi = l_hi * sl_hi + es_hi;
#pragma unroll
        for (int nf = 0; nf < NFV; nf++) {
            acc[nf][0] *= sl_lo; acc[nf][1] *= sl_lo;
            acc[nf][2] *= sl_hi; acc[nf][3] *= sl_hi;
        }
        __syncwarp();                          // P rows are warp-private

        // ---- PV: acc[16x96] += P[16x32] * V[32x96], 3xTF32
        const unsigned* Phu = (const unsigned*)Ph;
        const unsigned* Plu = (const unsigned*)Pl;
#pragma unroll
        for (int ks = 0; ks < 4; ks++) {
            int pc = ks * 8 + tig;
            unsigned ah0 = Phu[rlo * SPst + pc],     ah1 = Phu[rhi * SPst + pc];
            unsigned ah2 = Phu[rlo * SPst + pc + 4], ah3 = Phu[rhi * SPst + pc + 4];
            unsigned al0 = Plu[rlo * SPst + pc],     al1 = Plu[rhi * SPst + pc];
            unsigned al2 = Plu[rlo * SPst + pc + 4], al3 = Plu[rhi * SPst + pc + 4];
#pragma unroll
            for (int nf = 0; nf < NFV; nf++) {
                uint2 b0 = sV2[(ks * 8 + tig)     * 100 + nf * 8 + gid];
                uint2 b1 = sV2[(ks * 8 + tig + 4) * 100 + nf * 8 + gid];
                mma_tf32(acc[nf], ah0, ah1, ah2, ah3, b0.x, b1.x);
                mma_tf32(acc[nf], al0, al1, al2, al3, b0.x, b1.x);
                mma_tf32(acc[nf], ah0, ah1, ah2, ah3, b0.y, b1.y);
            }
        }
        __syncthreads();                       // all reads of buf[cur] done
    }

    float rl_lo = (l_lo > 0.f) ? 1.f / l_lo : 0.f;
    float rl_hi = (l_hi > 0.f) ? 1.f / l_hi : 0.f;
#pragma unroll
    for (int nf = 0; nf < NFV; nf++) {
        int d = nf * 8 + 2 * tig;
        int p = d >> 5, j = d & 31;
        *(float2*)&g_attn[((b * Tq + tlo) * Pq + p) * HIDq + h * 32 + j] =
            make_float2(acc[nf][0] * rl_lo, acc[nf][1] * rl_lo);
        *(float2*)&g_attn[((b * Tq + thi) * Pq + p) * HIDq + h * 32 + j] =
            make_float2(acc[nf][2] * rl_hi, acc[nf][3] * rl_hi);
    }
}

// ---------------------------------------------------------------------------
// inv + scale + bf16 hi/lo split: X = attn*lnw*inv -> k16 fragment rows.
// ---------------------------------------------------------------------------
__global__ __launch_bounds__(128) void inv_split_kernel(const float* __restrict__ lnw)
{
    const int bt = blockIdx.x;
    const float* a = &g_attn[bt * Pq * HIDq];
    const int tid = threadIdx.x;
    float s = 0.f;
    for (int i = tid; i < (Pq * HIDq) / 4; i += 128) {
        float4 x = *(const float4*)&a[i * 4];
        s = fmaf(x.x, x.x, s); s = fmaf(x.y, x.y, s);
        s = fmaf(x.z, x.z, s); s = fmaf(x.w, x.w, s);
    }
#pragma unroll
    for (int o = 16; o; o >>= 1) s += __shfl_xor_sync(0xffffffffu, s, o);
    __shared__ float ws[4];
    __shared__ float sInv;
    if ((tid & 31) == 0) ws[tid >> 5] = s;
    __syncthreads();
    if (tid == 0) {
        float tot = ws[0] + ws[1] + ws[2] + ws[3];
        sInv = rsqrtf(tot * (1.0f / (float)HIDq) + 1e-3f);
    }
    __syncthreads();
    const float inv = sInv;

    for (int u = tid; u < Pq * 128; u += 128) {
        int p = u >> 7, j = u & 127;
        int ks = j >> 2, tg = j & 3;
        int d0 = ks * 16 + 2 * tg;
        const float* ap = &a[p * HIDq + d0];
        float x0 = ap[0] * lnw[d0]     * inv;
        float x1 = ap[1] * lnw[d0 + 1] * inv;
        float x8 = ap[8] * lnw[d0 + 8] * inv;
        float x9 = ap[9] * lnw[d0 + 9] * inv;
        unsigned h0, l0, h1, l1;
        splitpack(x0, x1, h0, l0);
        splitpack(x8, x9, h1, l1);
        g_Xb[(bt * Pq + p) * 128 + j] = make_uint4(h0, h1, l0, l1);
    }
}

// ---------------------------------------------------------------------------
// Projection GEMM: out[m][n] = sum_k X[m][k]*W[n][k], 3xBF16 k16.
// Tile M=64 x N=128, K chunked by 64, double-buffered.
// ---------------------------------------------------------------------------
__global__ __launch_bounds__(256, 1) void proj_kernel(float* __restrict__ out)
{
    extern __shared__ __align__(16) char smembuf[];
    unsigned sbase;
    { unsigned long long p0 = __cvta_generic_to_shared(smembuf); sbase = (unsigned)p0; }

    const int bm = blockIdx.x, bn = blockIdx.y;
    const int tid  = threadIdx.x;
    const int warp = tid >> 5, lane = tid & 31;
    const int gid  = lane >> 2, tig = lane & 3;
    const int wm = warp & 3, wn = warp >> 2;

    auto load_chunk = [&](int c, int nb) {
        unsigned xb = sbase + P_OFF_X0 + nb * 20480;
        for (int i = tid; i < 1024; i += 256) {          // X: 64 rows x 16 u4
            int r = i >> 4, f = i & 15;
            cpa16(xb + (r * P_STR + f) * 16, &g_Xb[(bm * 64 + r) * 128 + c * 16 + f]);
        }
        unsigned wb = sbase + P_OFF_W0 + nb * 40960;
        for (int i = tid; i < 2048; i += 256) {          // W: 128 rows x 16 u4
            int r = i >> 4, f = i & 15;
            cpa16(wb + (r * P_STR + f) * 16, &g_Wb[(bn * 128 + r) * 128 + c * 16 + f]);
        }
    };

    float acc[8][4];
#pragma unroll
    for (int nf = 0; nf < 8; nf++)
#pragma unroll
        for (int i = 0; i < 4; i++) acc[nf][i] = 0.f;

    load_chunk(0, 0);
    cpa_commit();

    for (int c = 0; c < 8; c++) {
        const int cur = c & 1;
        if (c + 1 < 8) { load_chunk(c + 1, cur ^ 1); cpa_commit(); cpa_wait1(); }
        else           { cpa_wait0(); }
        __syncthreads();

        const uint4* Xs = (const uint4*)(smembuf + P_OFF_X0 + cur * 20480);
        const uint4* Wt = (const uint4*)(smembuf + P_OFF_W0 + cur * 40960);
#pragma unroll
        for (int ks = 0; ks < 4; ks++) {
            uint4 aL = Xs[(wm * 16 + gid)     * P_STR + ks * 4 + tig];
            uint4 aH = Xs[(wm * 16 + gid + 8) * P_STR + ks * 4 + tig];
#pragma unroll
            for (int nf = 0; nf < 8; nf++) {
                uint4 w4 = Wt[(wn * 64 + nf * 8 + gid) * P_STR + ks * 4 + tig];
                mma_bf16(acc[nf], aL.x, aH.x, aL.y, aH.y, w4.x, w4.y);  // hi*hi
                mma_bf16(acc[nf], aL.z, aH.z, aL.w, aH.w, w4.x, w4.y);  // lo*hi
                mma_bf16(acc[nf], aL.x, aH.x, aL.y, aH.y, w4.z, w4.w);  // hi*lo
            }
        }
        __syncthreads();
    }

    const int mlo = bm * 64 + wm * 16 + gid;
    const int mhi = mlo + 8;
#pragma unroll
    for (int nf = 0; nf < 8; nf++) {
        int col = bn * 128 + wn * 64 + nf * 8 + 2 * tig;
        *(float2*)&out[mlo * HIDq + col] = make_float2(acc[nf][0], acc[nf][1]);
        *(float2*)&out[mhi * HIDq + col] = make_float2(acc[nf][2], acc[nf][3]);
    }
}

// ---------------------------------------------------------------------------
extern "C" void kernel_launch(void* const* d_in, const int* in_sizes, int n_in,
                              void* d_out, int out_size)
{
    const float* q    = (const float*)d_in[0];
    const float* k    = (const float*)d_in[1];
    const float* v    = (const float*)d_in[2];
    const float* bias = (const float*)d_in[3];
    const unsigned char* kpm   = (const unsigned char*)d_in[4];
    const int*   outcell       = (const int*)d_in[5];
    const float* law  = (const float*)d_in[6];
    const unsigned char* emask = (const unsigned char*)d_in[7];
    const float* W    = (const float*)d_in[8];
    const float* lnw  = (const float*)d_in[9];
    float* out = (float*)d_out;

    cudaFuncSetAttribute(attn_kernel,
        cudaFuncAttributeMaxDynamicSharedMemorySize, A_SMEM);
    cudaFuncSetAttribute(proj_kernel,
        cudaFuncAttributeMaxDynamicSharedMemorySize, P_SMEM);

    int units = Bq * Tq * Hq * 48;
    presplit_kernel<<<(units + 255) / 256, 256>>>(k, v);
    presplit_w_kernel<<<(HIDq * 128 + 255) / 256, 256>>>(W);

    dim3 g1(Tq / TT, Hq, Bq);
    attn_kernel<<<g1, 256, A_SMEM>>>(q, bias, kpm, outcell, law, emask);

    inv_split_kernel<<<Bq * Tq, 128>>>(lnw);

    dim3 g3((Bq * Tq * Pq) / 64, HIDq / 128);
    proj_kernel<<<g3, 256, P_SMEM>>>(out);
}

// round 8
// speedup vs baseline: 4.0455x; 1.3162x over previous
#include <cuda_runtime.h>
#include <math.h>

#define Bq   4
#define Tq   512
#define Pq   3
#define HIDq 512
#define Hq   16
#define EXPq 512
#define Sq   1024
#define Dq   96

#define TT   128     // t rows per block (8 warps x 16)
#define TS   32      // s cols per tile
#define KS16 6       // Dq/16 k-steps for QK (bf16 k16)
#define NFV  12      // n-frags (8 cols each) for PV output
#define BLst 36      // bias/law smem row stride (floats)
#define KBst 28      // K smem row stride (uint4)
#define VROW 208     // V smem row stride (bytes) -> conflict-free ldmatrix

// ---- attn dynamic smem layout (bytes), double-buffered ----
#define A_OFF_K0 0         // uint4 [32 cols][28] : 14,336 per buf
#define A_OFF_V0 28672     // bf16 hi plane [32][208B] + lo plane : 13,312 per buf
#define A_OFF_B0 55296     // float [128][36] : 18,432 per buf
#define A_OFF_L0 92160     // float [128][36] : 18,432 per buf
#define A_OFF_DD 129024    // uchar [2][32]
#define A_SMEM   129088

// ---- proj dynamic smem layout (bf16 k16): X/W tiles, double-buffered ----
#define P_STR    20        // uint4 row stride
#define P_OFF_X0 0         // uint4 [64][20]  : 20,480 per buf
#define P_OFF_W0 40960     // uint4 [128][20] : 40,960 per buf
#define P_SMEM   122880

// Pre-split storage:
// g_Kb[bth*24 + ks*4 + tig] = (b0h,b1h,b0l,b1l) bf16x2 frags, k-pair d=16ks+2tig
// g_Vb[bth*96]: uints 0-47 = hi bf16 pairs (d,d+1), 48-95 = lo pairs (384B/row)
// g_Xb, g_Wb: k16 bf16 hi/lo fragment rows for proj
__device__ uint4    g_Kb[Bq * Tq * Hq * 24];
__device__ unsigned g_Vb[Bq * Tq * Hq * 96];
__device__ float    g_attn[Bq * Tq * Pq * HIDq];
__device__ uint4    g_Xb[Bq * Tq * Pq * 128];
__device__ uint4    g_Wb[HIDq * 128];

__device__ __forceinline__ unsigned packbf(float lo, float hi) {
    unsigned d; asm("cvt.rn.bf16x2.f32 %0,%1,%2;" : "=r"(d) : "f"(hi), "f"(lo));
    return d;
}
// bf16 hi/lo split of a value pair, packed bf16x2 (low 16 bits = first value).
__device__ __forceinline__ void splitpack(float x0, float x1, unsigned& h, unsigned& l) {
    h = packbf(x0, x1);
    float h0 = __uint_as_float(h << 16);
    float h1 = __uint_as_float(h & 0xffff0000u);
    l = packbf(x0 - h0, x1 - h1);
}
__device__ __forceinline__ void mma_bf16(float* c,
    unsigned a0, unsigned a1, unsigned a2, unsigned a3,
    unsigned b0, unsigned b1)
{
    asm volatile(
        "mma.sync.aligned.m16n8k16.row.col.f32.bf16.bf16.f32 "
        "{%0,%1,%2,%3},{%4,%5,%6,%7},{%8,%9},{%0,%1,%2,%3};"
        : "+f"(c[0]), "+f"(c[1]), "+f"(c[2]), "+f"(c[3])
        : "r"(a0), "r"(a1), "r"(a2), "r"(a3), "r"(b0), "r"(b1));
}
__device__ __forceinline__ void ldsm4t(uint4& v, unsigned a) {
    asm volatile(
        "ldmatrix.sync.aligned.m8n8.x4.trans.shared.b16 {%0,%1,%2,%3}, [%4];"
        : "=r"(v.x), "=r"(v.y), "=r"(v.z), "=r"(v.w) : "r"(a));
}
__device__ __forceinline__ void cpa16(unsigned dst, const void* src) {
    asm volatile("cp.async.cg.shared.global [%0], [%1], 16;\n" :: "r"(dst), "l"(src));
}
__device__ __forceinline__ void cpa_commit() {
    asm volatile("cp.async.commit_group;\n" ::: "memory");
}
__device__ __forceinline__ void cpa_wait1() {
    asm volatile("cp.async.wait_group 1;\n" ::: "memory");
}
__device__ __forceinline__ void cpa_wait0() {
    asm volatile("cp.async.wait_group 0;\n" ::: "memory");
}

// ---------------------------------------------------------------------------
// One-time presplit: K -> bf16 hi/lo k16 B-frags; V -> bf16 hi/lo planes.
// ---------------------------------------------------------------------------
__global__ __launch_bounds__(256) void presplit_kernel(
    const float* __restrict__ k, const float* __restrict__ v)
{
    int gidx = blockIdx.x * 256 + threadIdx.x;
    const int U = 48;
    if (gidx >= Bq * Tq * Hq * U) return;
    int u = gidx % U;
    int bth = gidx / U;
    int h = bth % Hq;
    int bt = bth / Hq;

    if (u < 24) {
        int ks = u >> 2, tg = u & 3;
        int d0 = ks * 16 + 2 * tg;
        const float* src = &k[(bt * Pq + (d0 >> 5)) * HIDq + h * 32 + (d0 & 31)];
        float2 e01 = *(const float2*)src;
        float2 e89 = *(const float2*)(src + 8);
        unsigned b0h, b0l, b1h, b1l;
        splitpack(e01.x, e01.y, b0h, b0l);
        splitpack(e89.x, e89.y, b1h, b1l);
        g_Kb[bth * 24 + u] = make_uint4(b0h, b1h, b0l, b1l);
    } else {
        int d = (u - 24) * 4;
        float4 x = *(const float4*)&v[(bt * Pq + (d >> 5)) * HIDq + h * 32 + (d & 31)];
        unsigned h0, l0, h1, l1;
        splitpack(x.x, x.y, h0, l0);
        splitpack(x.z, x.w, h1, l1);
        unsigned* dst = &g_Vb[bth * 96];
        dst[d / 2]          = h0;
        dst[d / 2 + 1]      = h1;
        dst[48 + d / 2]     = l0;
        dst[48 + d / 2 + 1] = l1;
    }
}

// ---------------------------------------------------------------------------
// One-time W bf16 hi/lo split into k16 fragment rows.
// ---------------------------------------------------------------------------
__global__ __launch_bounds__(256) void presplit_w_kernel(const float* __restrict__ W)
{
    int g = blockIdx.x * 256 + threadIdx.x;
    if (g >= HIDq * 128) return;
    int n = g >> 7, j = g & 127;
    int ks = j >> 2, tg = j & 3;
    int d0 = ks * 16 + 2 * tg;
    const float* src = &W[n * HIDq + d0];
    float2 e01 = *(const float2*)src;
    float2 e89 = *(const float2*)(src + 8);
    unsigned b0h, b0l, b1h, b1l;
    splitpack(e01.x, e01.y, b0h, b0l);
    splitpack(e89.x, e89.y, b1h, b1l);
    g_Wb[n * 128 + j] = make_uint4(b0h, b1h, b0l, b1l);
}

// ---------------------------------------------------------------------------
// Fused gather + flash attention: QK and PV both 3xBF16 k16.
// P stays in registers (A-fragment layout == softmax compute layout);
// V comes through ldmatrix.trans from row-per-s smem planes.
// ---------------------------------------------------------------------------
__global__ __launch_bounds__(256, 1) void attn_kernel(
    const float* __restrict__ q, const float* __restrict__ bias,
    const unsigned char* __restrict__ kpm, const int* __restrict__ outcell,
    const float* __restrict__ law, const unsigned char* __restrict__ emask)
{
    extern __shared__ __align__(16) char smembuf[];
    unsigned char* sDead = (unsigned char*)(smembuf + A_OFF_DD);
    unsigned sbase;
    { unsigned long long p0 = __cvta_generic_to_shared(smembuf); sbase = (unsigned)p0; }

    const int b  = blockIdx.z, h = blockIdx.y;
    const int t0 = blockIdx.x * TT;
    const int tid  = threadIdx.x;
    const int warp = tid >> 5, lane = tid & 31;
    const int gid  = lane >> 2, tig = lane & 3;
    const int rowBase = warp * 16;
    const int rlo = rowBase + gid, rhi = rlo + 8;
    const int tlo = t0 + rlo,      thi = t0 + rhi;

    // ldmatrix per-lane address pieces: 4 matrices (2 k-halves x 2 n-groups)
    const int vrow = ((lane >> 3) & 1) * 8 + (lane & 7);   // s-row within 16
    const int ncb  = (lane >> 4) * 8;                      // n col base (0 or 8)

    // Preload Q A-fragments (bf16 hi/lo, k16).
    unsigned qh[KS16][4], ql[KS16][4];
#pragma unroll
    for (int ks = 0; ks < KS16; ks++) {
        int d0 = ks * 16 + 2 * tig;
        int baseL = ((b * Tq + tlo) * Pq + (d0 >> 5)) * HIDq + h * 32 + (d0 & 31);
        int baseH = ((b * Tq + thi) * Pq + (d0 >> 5)) * HIDq + h * 32 + (d0 & 31);
        float2 qa = *(const float2*)&q[baseL];
        float2 qb = *(const float2*)&q[baseH];
        float2 qc = *(const float2*)&q[baseL + 8];
        float2 qd = *(const float2*)&q[baseH + 8];
        splitpack(qa.x, qa.y, qh[ks][0], ql[ks][0]);
        splitpack(qb.x, qb.y, qh[ks][1], ql[ks][1]);
        splitpack(qc.x, qc.y, qh[ks][2], ql[ks][2]);
        splitpack(qd.x, qd.y, qh[ks][3], ql[ks][3]);
    }

    float m_lo = -3.0e38f, m_hi = -3.0e38f, l_lo = 0.f, l_hi = 0.f;
    float acc[NFV][4];
#pragma unroll
    for (int nf = 0; nf < NFV; nf++)
#pragma unroll
        for (int i = 0; i < 4; i++) acc[nf][i] = 0.f;

    auto issue_tile = [&](int it, int nb) {
        int s0t = it * TS;
        unsigned kb = sbase + A_OFF_K0 + nb * 14336;
        unsigned vb = sbase + A_OFF_V0 + nb * 13312;
        for (int i = tid; i < 768; i += 256) {            // K: 32 x 24 chunks
            int c = i / 24, f = i - c * 24;
            int s = s0t + c;
            int ts = (s < Tq) ? s : outcell[b * EXPq + (s - Tq)];
            cpa16(kb + c * 448 + f * 16, &g_Kb[((b * Tq + ts) * Hq + h) * 24 + f]);
        }
        for (int i = tid; i < 768; i += 256) {            // V: 32 x 24 chunks
            int c = i / 24, f = i - c * 24;
            int s = s0t + c;
            int ts = (s < Tq) ? s : outcell[b * EXPq + (s - Tq)];
            const char* src = (const char*)&g_Vb[((b * Tq + ts) * Hq + h) * 96] + f * 16;
            unsigned dst = (f < 12) ? (vb + c * VROW + f * 16)
                                    : (vb + 6656 + c * VROW + (f - 12) * 16);
            cpa16(dst, src);
        }
        unsigned bb = sbase + A_OFF_B0 + nb * 18432;
        unsigned lb = sbase + A_OFF_L0 + nb * 18432;
        const float* bsrc = &bias[((b * Hq + h) * Tq + t0) * Sq + s0t];
        const float* lsrc = &law [(b * Tq + t0) * Sq + s0t];
        for (int i = tid; i < 1024; i += 256) {
            int r = i >> 3, f = i & 7;
            cpa16(bb + r * (BLst * 4) + f * 16, bsrc + r * Sq + f * 4);
            cpa16(lb + r * (BLst * 4) + f * 16, lsrc + r * Sq + f * 4);
        }
        if (tid < TS) {
            int s = s0t + tid;
            sDead[nb * 32 + tid] =
                (s < Tq) ? kpm[b * Tq + s] : emask[b * EXPq + (s - Tq)];
        }
    };

    issue_tile(0, 0);
    cpa_commit();

    for (int it = 0; it < Sq / TS; it++) {
        const int cur = it & 1;
        if (it + 1 < Sq / TS) { issue_tile(it + 1, cur ^ 1); cpa_commit(); cpa_wait1(); }
        else                  { cpa_wait0(); }
        __syncthreads();

        const uint4* sKb = (const uint4*)(smembuf + A_OFF_K0 + cur * 14336);
        const unsigned vB = sbase + A_OFF_V0 + cur * 13312;
        const float* sB  = (const float*)(smembuf + A_OFF_B0 + cur * 18432);
        const float* sL  = (const float*)(smembuf + A_OFF_L0 + cur * 18432);

        // ---- scores: C[16x32] per warp, 3xBF16 k16
        float sc[4][4];
#pragma unroll
        for (int nf = 0; nf < 4; nf++)
#pragma unroll
            for (int i = 0; i < 4; i++) sc[nf][i] = 0.f;
#pragma unroll
        for (int ks = 0; ks < KS16; ks++) {
#pragma unroll
            for (int nf = 0; nf < 4; nf++) {
                uint4 bb = sKb[(nf * 8 + gid) * KBst + ks * 4 + tig];
                mma_bf16(sc[nf], qh[ks][0], qh[ks][1], qh[ks][2], qh[ks][3], bb.x, bb.y);
                mma_bf16(sc[nf], ql[ks][0], ql[ks][1], ql[ks][2], ql[ks][3], bb.x, bb.y);
                mma_bf16(sc[nf], qh[ks][0], qh[ks][1], qh[ks][2], qh[ks][3], bb.z, bb.w);
            }
        }

        // ---- bias + masks + online softmax (LDS-only operands)
        float pw[4][4];
        float lmax_lo = -3.0e38f, lmax_hi = -3.0e38f;
#pragma unroll
        for (int nf = 0; nf < 4; nf++) {
            int colL = nf * 8 + 2 * tig;
            float2 blo = *(const float2*)&sB[rlo * BLst + colL];
            float2 bhi = *(const float2*)&sB[rhi * BLst + colL];
            float2 wlo = *(const float2*)&sL[rlo * BLst + colL];
            float2 whi = *(const float2*)&sL[rhi * BLst + colL];
            unsigned char d0 = sDead[cur * 32 + colL], d1 = sDead[cur * 32 + colL + 1];

            float x, lw;
            x = sc[nf][0] + blo.x; lw = wlo.x;
            if (d0 || lw <= 1e-5f) { x = -3.0e38f; lw = 0.f; }
            sc[nf][0] = x; pw[nf][0] = lw; lmax_lo = fmaxf(lmax_lo, x);
            x = sc[nf][1] + blo.y; lw = wlo.y;
            if (d1 || lw <= 1e-5f) { x = -3.0e38f; lw = 0.f; }
            sc[nf][1] = x; pw[nf][1] = lw; lmax_lo = fmaxf(lmax_lo, x);
            x = sc[nf][2] + bhi.x; lw = whi.x;
            if (d0 || lw <= 1e-5f) { x = -3.0e38f; lw = 0.f; }
            sc[nf][2] = x; pw[nf][2] = lw; lmax_hi = fmaxf(lmax_hi, x);
            x = sc[nf][3] + bhi.y; lw = whi.y;
            if (d1 || lw <= 1e-5f) { x = -3.0e38f; lw = 0.f; }
            sc[nf][3] = x; pw[nf][3] = lw; lmax_hi = fmaxf(lmax_hi, x);
        }
#pragma unroll
        for (int o = 1; o < 4; o <<= 1) {
            lmax_lo = fmaxf(lmax_lo, __shfl_xor_sync(0xffffffffu, lmax_lo, o));
            lmax_hi = fmaxf(lmax_hi, __shfl_xor_sync(0xffffffffu, lmax_hi, o));
        }
        float nm_lo = fmaxf(m_lo, lmax_lo), nm_hi = fmaxf(m_hi, lmax_hi);
        float sl_lo = __expf(m_lo - nm_lo),  sl_hi = __expf(m_hi - nm_hi);
        m_lo = nm_lo; m_hi = nm_hi;

        // ---- P = exp(w-m)*law, packed bf16 hi/lo pairs IN REGISTERS.
        // A-fragment layout of m16n8k16 matches compute layout exactly.
        unsigned pH[4][2], pL[4][2];
        float es_lo = 0.f, es_hi = 0.f;
#pragma unroll
        for (int nf = 0; nf < 4; nf++) {
            float e0 = __expf(sc[nf][0] - nm_lo); es_lo += e0;
            float e1 = __expf(sc[nf][1] - nm_lo); es_lo += e1;
            float e2 = __expf(sc[nf][2] - nm_hi); es_hi += e2;
            float e3 = __expf(sc[nf][3] - nm_hi); es_hi += e3;
            float p0 = e0 * pw[nf][0], p1 = e1 * pw[nf][1];
            float p2 = e2 * pw[nf][2], p3 = e3 * pw[nf][3];
            splitpack(p0, p1, pH[nf][0], pL[nf][0]);   // rlo pair
            splitpack(p2, p3, pH[nf][1], pL[nf][1]);   // rhi pair
        }
#pragma unroll
        for (int o = 1; o < 4; o <<= 1) {
            es_lo += __shfl_xor_sync(0xffffffffu, es_lo, o);
            es_hi += __shfl_xor_sync(0xffffffffu, es_hi, o);
        }
        l_lo = l_lo * sl_lo + es_lo;
        l_hi = l_hi * sl_hi + es_hi;
#pragma unroll
        for (int nf = 0; nf < NFV; nf++) {
            acc[nf][0] *= sl_lo; acc[nf][1] *= sl_lo;
            acc[nf][2] *= sl_hi; acc[nf][3] *= sl_hi;
        }

        // ---- PV: acc[16x96] += P[16x32] * V[32x96], 3xBF16 k16 via ldmatrix
#pragma unroll
        for (int ks2 = 0; ks2 < 2; ks2++) {
            unsigned ah0 = pH[2 * ks2][0],     ah1 = pH[2 * ks2][1];
            unsigned ah2 = pH[2 * ks2 + 1][0], ah3 = pH[2 * ks2 + 1][1];
            unsigned al0 = pL[2 * ks2][0],     al1 = pL[2 * ks2][1];
            unsigned al2 = pL[2 * ks2 + 1][0], al3 = pL[2 * ks2 + 1][1];
            unsigned abase = vB + (16 * ks2 + vrow) * VROW + ncb * 2;
#pragma unroll
            for (int j = 0; j < 6; j++) {
                uint4 vh, vl;
                ldsm4t(vh, abase + j * 32);
                ldsm4t(vl, abase + j * 32 + 6656);
                mma_bf16(acc[2 * j],     ah0, ah1, ah2, ah3, vh.x, vh.y);
                mma_bf16(acc[2 * j],     al0, al1, al2, al3, vh.x, vh.y);
                mma_bf16(acc[2 * j],     ah0, ah1, ah2, ah3, vl.x, vl.y);
                mma_bf16(acc[2 * j + 1], ah0, ah1, ah2, ah3, vh.z, vh.w);
                mma_bf16(acc[2 * j + 1], al0, al1, al2, al3, vh.z, vh.w);
                mma_bf16(acc[2 * j + 1], ah0, ah1, ah2, ah3, vl.z, vl.w);
            }
        }
        __syncthreads();                       // all reads of buf[cur] done
    }

    float rl_lo = (l_lo > 0.f) ? 1.f / l_lo : 0.f;
    float rl_hi = (l_hi > 0.f) ? 1.f / l_hi : 0.f;
#pragma unroll
    for (int nf = 0; nf < NFV; nf++) {
        int d = nf * 8 + 2 * tig;
        int p = d >> 5, j = d & 31;
        *(float2*)&g_attn[((b * Tq + tlo) * Pq + p) * HIDq + h * 32 + j] =
            make_float2(acc[nf][0] * rl_lo, acc[nf][1] * rl_lo);
        *(float2*)&g_attn[((b * Tq + thi) * Pq + p) * HIDq + h * 32 + j] =
            make_float2(acc[nf][2] * rl_hi, acc[nf][3] * rl_hi);
    }
}

// ---------------------------------------------------------------------------
// inv + scale + bf16 hi/lo split: X = attn*lnw*inv -> k16 fragment rows.
// ---------------------------------------------------------------------------
__global__ __launch_bounds__(128) void inv_split_kernel(const float* __restrict__ lnw)
{
    const int bt = blockIdx.x;
    const float* a = &g_attn[bt * Pq * HIDq];
    const int tid = threadIdx.x;
    float s = 0.f;
    for (int i = tid; i < (Pq * HIDq) / 4; i += 128) {
        float4 x = *(const float4*)&a[i * 4];
        s = fmaf(x.x, x.x, s); s = fmaf(x.y, x.y, s);
        s = fmaf(x.z, x.z, s); s = fmaf(x.w, x.w, s);
    }
#pragma unroll
    for (int o = 16; o; o >>= 1) s += __shfl_xor_sync(0xffffffffu, s, o);
    __shared__ float ws[4];
    __shared__ float sInv;
    if ((tid & 31) == 0) ws[tid >> 5] = s;
    __syncthreads();
    if (tid == 0) {
        float tot = ws[0] + ws[1] + ws[2] + ws[3];
        sInv = rsqrtf(tot * (1.0f / (float)HIDq) + 1e-3f);
    }
    __syncthreads();
    const float inv = sInv;

    for (int u = tid; u < Pq * 128; u += 128) {
        int p = u >> 7, j = u & 127;
        int ks = j >> 2, tg = j & 3;
        int d0 = ks * 16 + 2 * tg;
        const float* ap = &a[p * HIDq + d0];
        float x0 = ap[0] * lnw[d0]     * inv;
        float x1 = ap[1] * lnw[d0 + 1] * inv;
        float x8 = ap[8] * lnw[d0 + 8] * inv;
        float x9 = ap[9] * lnw[d0 + 9] * inv;
        unsigned h0, l0, h1, l1;
        splitpack(x0, x1, h0, l0);
        splitpack(x8, x9, h1, l1);
        g_Xb[(bt * Pq + p) * 128 + j] = make_uint4(h0, h1, l0, l1);
    }
}

// ---------------------------------------------------------------------------
// Projection GEMM: out[m][n] = sum_k X[m][k]*W[n][k], 3xBF16 k16.
// ---------------------------------------------------------------------------
__global__ __launch_bounds__(256, 1) void proj_kernel(float* __restrict__ out)
{
    extern __shared__ __align__(16) char smembuf[];
    unsigned sbase;
    { unsigned long long p0 = __cvta_generic_to_shared(smembuf); sbase = (unsigned)p0; }

    const int bm = blockIdx.x, bn = blockIdx.y;
    const int tid  = threadIdx.x;
    const int warp = tid >> 5, lane = tid & 31;
    const int gid  = lane >> 2, tig = lane & 3;
    const int wm = warp & 3, wn = warp >> 2;

    auto load_chunk = [&](int c, int nb) {
        unsigned xb = sbase + P_OFF_X0 + nb * 20480;
        for (int i = tid; i < 1024; i += 256) {
            int r = i >> 4, f = i & 15;
            cpa16(xb + (r * P_STR + f) * 16, &g_Xb[(bm * 64 + r) * 128 + c * 16 + f]);
        }
        unsigned wb = sbase + P_OFF_W0 + nb * 40960;
        for (int i = tid; i < 2048; i += 256) {
            int r = i >> 4, f = i & 15;
            cpa16(wb + (r * P_STR + f) * 16, &g_Wb[(bn * 128 + r) * 128 + c * 16 + f]);
        }
    };

    float acc[8][4];
#pragma unroll
    for (int nf = 0; nf < 8; nf++)
#pragma unroll
        for (int i = 0; i < 4; i++) acc[nf][i] = 0.f;

    load_chunk(0, 0);
    cpa_commit();

    for (int c = 0; c < 8; c++) {
        const int cur = c & 1;
        if (c + 1 < 8) { load_chunk(c + 1, cur ^ 1); cpa_commit(); cpa_wait1(); }
        else           { cpa_wait0(); }
        __syncthreads();

        const uint4* Xs = (const uint4*)(smembuf + P_OFF_X0 + cur * 20480);
        const uint4* Wt = (const uint4*)(smembuf + P_OFF_W0 + cur * 40960);
#pragma unroll
        for (int ks = 0; ks < 4; ks++) {
            uint4 aL = Xs[(wm * 16 + gid)     * P_STR + ks * 4 + tig];
            uint4 aH = Xs[(wm * 16 + gid + 8) * P_STR + ks * 4 + tig];
#pragma unroll
            for (int nf = 0; nf < 8; nf++) {
                uint4 w4 = Wt[(wn * 64 + nf * 8 + gid) * P_STR + ks * 4 + tig];
                mma_bf16(acc[nf], aL.x, aH.x, aL.y, aH.y, w4.x, w4.y);
                mma_bf16(acc[nf], aL.z, aH.z, aL.w, aH.w, w4.x, w4.y);
                mma_bf16(acc[nf], aL.x, aH.x, aL.y, aH.y, w4.z, w4.w);
            }
        }
        __syncthreads();
    }

    const int mlo = bm * 64 + wm * 16 + gid;
    const int mhi = mlo + 8;
#pragma unroll
    for (int nf = 0; nf < 8; nf++) {
        int col = bn * 128 + wn * 64 + nf * 8 + 2 * tig;
        *(float2*)&out[mlo * HIDq + col] = make_float2(acc[nf][0], acc[nf][1]);
        *(float2*)&out[mhi * HIDq + col] = make_float2(acc[nf][2], acc[nf][3]);
    }
}

// ---------------------------------------------------------------------------
extern "C" void kernel_launch(void* const* d_in, const int* in_sizes, int n_in,
                              void* d_out, int out_size)
{
    const float* q    = (const float*)d_in[0];
    const float* k    = (const float*)d_in[1];
    const float* v    = (const float*)d_in[2];
    const float* bias = (const float*)d_in[3];
    const unsigned char* kpm   = (const unsigned char*)d_in[4];
    const int*   outcell       = (const int*)d_in[5];
    const float* law  = (const float*)d_in[6];
    const unsigned char* emask = (const unsigned char*)d_in[7];
    const float* W    = (const float*)d_in[8];
    const float* lnw  = (const float*)d_in[9];
    float* out = (float*)d_out;

    cudaFuncSetAttribute(attn_kernel,
        cudaFuncAttributeMaxDynamicSharedMemorySize, A_SMEM);
    cudaFuncSetAttribute(proj_kernel,
        cudaFuncAttributeMaxDynamicSharedMemorySize, P_SMEM);

    int units = Bq * Tq * Hq * 48;
    presplit_kernel<<<(units + 255) / 256, 256>>>(k, v);
    presplit_w_kernel<<<(HIDq * 128 + 255) / 256, 256>>>(W);

    dim3 g1(Tq / TT, Hq, Bq);
    attn_kernel<<<g1, 256, A_SMEM>>>(q, bias, kpm, outcell, law, emask);

    inv_split_kernel<<<Bq * Tq, 128>>>(lnw);

    dim3 g3((Bq * Tq * Pq) / 64, HIDq / 128);
    proj_kernel<<<g3, 256, P_SMEM>>>(out);
}

// round 9
// speedup vs baseline: 4.2627x; 1.0537x over previous
#include <cuda_runtime.h>
#include <cuda_fp16.h>
#include <math.h>

#define Bq   4
#define Tq   512
#define Pq   3
#define HIDq 512
#define Hq   16
#define EXPq 512
#define Sq   1024
#define Dq   96

#define TT   128     // t rows per block (8 warps x 16)
#define TS   32      // s cols per tile
#define KS16 6       // Dq/16 k-steps for QK (bf16 k16)
#define NFV  12      // n-frags (8 cols each) for PV output
#define BLst 36      // bias/law smem row stride (floats)
#define KBst 28      // K smem row stride (uint4)
#define VROW 208     // V smem row stride (bytes) -> conflict-free ldmatrix

// ---- attn dynamic smem layout (bytes), double-buffered ----
#define A_OFF_K0 0         // uint4 [32 cols][28] : 14,336 per buf
#define A_OFF_V0 28672     // fp16 plane [32][208B] : 6,656 per buf
#define A_OFF_B0 41984     // float [128][36] : 18,432 per buf
#define A_OFF_L0 78848     // float [128][36] : 18,432 per buf
#define A_OFF_DD 115712    // uchar [2][32]
#define A_SMEM   115776

// ---- proj dynamic smem layout (bf16 k16): X/W tiles, double-buffered ----
#define P_STR    20        // uint4 row stride
#define P_OFF_X0 0         // uint4 [64][20]  : 20,480 per buf
#define P_OFF_W0 40960     // uint4 [128][20] : 40,960 per buf
#define P_SMEM   122880

// Pre-split storage:
// g_Kb[bth*24 + ks*4 + tig] = (b0h,b1h,b0l,b1l) bf16x2 frags, k-pair d=16ks+2tig
// g_Vh[bth*48 + d/2] = fp16x2 pair (v_d, v_{d+1})           (192 B per (bt,h))
// g_Xb, g_Wb: k16 bf16 hi/lo fragment rows for proj
__device__ uint4    g_Kb[Bq * Tq * Hq * 24];
__device__ unsigned g_Vh[Bq * Tq * Hq * 48];
__device__ float    g_attn[Bq * Tq * Pq * HIDq];
__device__ uint4    g_Xb[Bq * Tq * Pq * 128];
__device__ uint4    g_Wb[HIDq * 128];

__device__ __forceinline__ unsigned packbf(float lo, float hi) {
    unsigned d; asm("cvt.rn.bf16x2.f32 %0,%1,%2;" : "=r"(d) : "f"(hi), "f"(lo));
    return d;
}
// bf16 hi/lo split of a value pair, packed bf16x2 (low 16 bits = first value).
__device__ __forceinline__ void splitpack(float x0, float x1, unsigned& h, unsigned& l) {
    h = packbf(x0, x1);
    float h0 = __uint_as_float(h << 16);
    float h1 = __uint_as_float(h & 0xffff0000u);
    l = packbf(x0 - h0, x1 - h1);
}
// fp16 hi/lo split of a value pair, packed f16x2 (low half = first value).
__device__ __forceinline__ void splitpack16(float x0, float x1, unsigned& h, unsigned& l) {
    __half2 hh = __floats2half2_rn(x0, x1);
    h = *reinterpret_cast<unsigned*>(&hh);
    float h0 = __low2float(hh), h1 = __high2float(hh);
    __half2 ll = __floats2half2_rn(x0 - h0, x1 - h1);
    l = *reinterpret_cast<unsigned*>(&ll);
}
__device__ __forceinline__ unsigned pack16(float x0, float x1) {
    __half2 hh = __floats2half2_rn(x0, x1);
    return *reinterpret_cast<unsigned*>(&hh);
}
__device__ __forceinline__ void mma_bf16(float* c,
    unsigned a0, unsigned a1, unsigned a2, unsigned a3,
    unsigned b0, unsigned b1)
{
    asm volatile(
        "mma.sync.aligned.m16n8k16.row.col.f32.bf16.bf16.f32 "
        "{%0,%1,%2,%3},{%4,%5,%6,%7},{%8,%9},{%0,%1,%2,%3};"
        : "+f"(c[0]), "+f"(c[1]), "+f"(c[2]), "+f"(c[3])
        : "r"(a0), "r"(a1), "r"(a2), "r"(a3), "r"(b0), "r"(b1));
}
__device__ __forceinline__ void mma_f16(float* c,
    unsigned a0, unsigned a1, unsigned a2, unsigned a3,
    unsigned b0, unsigned b1)
{
    asm volatile(
        "mma.sync.aligned.m16n8k16.row.col.f32.f16.f16.f32 "
        "{%0,%1,%2,%3},{%4,%5,%6,%7},{%8,%9},{%0,%1,%2,%3};"
        : "+f"(c[0]), "+f"(c[1]), "+f"(c[2]), "+f"(c[3])
        : "r"(a0), "r"(a1), "r"(a2), "r"(a3), "r"(b0), "r"(b1));
}
__device__ __forceinline__ void ldsm4t(uint4& v, unsigned a) {
    asm volatile(
        "ldmatrix.sync.aligned.m8n8.x4.trans.shared.b16 {%0,%1,%2,%3}, [%4];"
        : "=r"(v.x), "=r"(v.y), "=r"(v.z), "=r"(v.w) : "r"(a));
}
__device__ __forceinline__ void cpa16(unsigned dst, const void* src) {
    asm volatile("cp.async.cg.shared.global [%0], [%1], 16;\n" :: "r"(dst), "l"(src));
}
__device__ __forceinline__ void cpa_commit() {
    asm volatile("cp.async.commit_group;\n" ::: "memory");
}
__device__ __forceinline__ void cpa_wait1() {
    asm volatile("cp.async.wait_group 1;\n" ::: "memory");
}
__device__ __forceinline__ void cpa_wait0() {
    asm volatile("cp.async.wait_group 0;\n" ::: "memory");
}

// ---------------------------------------------------------------------------
// One-time presplit: K -> bf16 hi/lo k16 B-frags; V -> fp16 pairs (single plane).
// ---------------------------------------------------------------------------
__global__ __launch_bounds__(256) void presplit_kernel(
    const float* __restrict__ k, const float* __restrict__ v)
{
    int gidx = blockIdx.x * 256 + threadIdx.x;
    const int U = 48;
    if (gidx >= Bq * Tq * Hq * U) return;
    int u = gidx % U;
    int bth = gidx / U;
    int h = bth % Hq;
    int bt = bth / Hq;

    if (u < 24) {
        int ks = u >> 2, tg = u & 3;
        int d0 = ks * 16 + 2 * tg;
        const float* src = &k[(bt * Pq + (d0 >> 5)) * HIDq + h * 32 + (d0 & 31)];
        float2 e01 = *(const float2*)src;
        float2 e89 = *(const float2*)(src + 8);
        unsigned b0h, b0l, b1h, b1l;
        splitpack(e01.x, e01.y, b0h, b0l);
        splitpack(e89.x, e89.y, b1h, b1l);
        g_Kb[bth * 24 + u] = make_uint4(b0h, b1h, b0l, b1l);
    } else {
        int d = (u - 24) * 4;
        float4 x = *(const float4*)&v[(bt * Pq + (d >> 5)) * HIDq + h * 32 + (d & 31)];
        unsigned* dst = &g_Vh[bth * 48 + d / 2];
        dst[0] = pack16(x.x, x.y);
        dst[1] = pack16(x.z, x.w);
    }
}

// ---------------------------------------------------------------------------
// One-time W bf16 hi/lo split into k16 fragment rows.
// ---------------------------------------------------------------------------
__global__ __launch_bounds__(256) void presplit_w_kernel(const float* __restrict__ W)
{
    int g = blockIdx.x * 256 + threadIdx.x;
    if (g >= HIDq * 128) return;
    int n = g >> 7, j = g & 127;
    int ks = j >> 2, tg = j & 3;
    int d0 = ks * 16 + 2 * tg;
    const float* src = &W[n * HIDq + d0];
    float2 e01 = *(const float2*)src;
    float2 e89 = *(const float2*)(src + 8);
    unsigned b0h, b0l, b1h, b1l;
    splitpack(e01.x, e01.y, b0h, b0l);
    splitpack(e89.x, e89.y, b1h, b1l);
    g_Wb[n * 128 + j] = make_uint4(b0h, b1h, b0l, b1l);
}

// ---------------------------------------------------------------------------
// Fused gather + flash attention: QK 3xBF16 k16, PV 2-term FP16 k16.
// P stays in registers (A-frag layout == softmax layout); V via ldmatrix.trans.
// ---------------------------------------------------------------------------
__global__ __launch_bounds__(256, 1) void attn_kernel(
    const float* __restrict__ q, const float* __restrict__ bias,
    const unsigned char* __restrict__ kpm, const int* __restrict__ outcell,
    const float* __restrict__ law, const unsigned char* __restrict__ emask)
{
    extern __shared__ __align__(16) char smembuf[];
    unsigned char* sDead = (unsigned char*)(smembuf + A_OFF_DD);
    unsigned sbase;
    { unsigned long long p0 = __cvta_generic_to_shared(smembuf); sbase = (unsigned)p0; }

    const int b  = blockIdx.z, h = blockIdx.y;
    const int t0 = blockIdx.x * TT;
    const int tid  = threadIdx.x;
    const int warp = tid >> 5, lane = tid & 31;
    const int gid  = lane >> 2, tig = lane & 3;
    const int rowBase = warp * 16;
    const int rlo = rowBase + gid, rhi = rlo + 8;
    const int tlo = t0 + rlo,      thi = t0 + rhi;

    // ldmatrix per-lane address pieces
    const int vrow = ((lane >> 3) & 1) * 8 + (lane & 7);
    const int ncb  = (lane >> 4) * 8;

    // Preload Q A-fragments (bf16 hi/lo, k16).
    unsigned qh[KS16][4], ql[KS16][4];
#pragma unroll
    for (int ks = 0; ks < KS16; ks++) {
        int d0 = ks * 16 + 2 * tig;
        int baseL = ((b * Tq + tlo) * Pq + (d0 >> 5)) * HIDq + h * 32 + (d0 & 31);
        int baseH = ((b * Tq + thi) * Pq + (d0 >> 5)) * HIDq + h * 32 + (d0 & 31);
        float2 qa = *(const float2*)&q[baseL];
        float2 qb = *(const float2*)&q[baseH];
        float2 qc = *(const float2*)&q[baseL + 8];
        float2 qd = *(const float2*)&q[baseH + 8];
        splitpack(qa.x, qa.y, qh[ks][0], ql[ks][0]);
        splitpack(qb.x, qb.y, qh[ks][1], ql[ks][1]);
        splitpack(qc.x, qc.y, qh[ks][2], ql[ks][2]);
        splitpack(qd.x, qd.y, qh[ks][3], ql[ks][3]);
    }

    float m_lo = -3.0e38f, m_hi = -3.0e38f, l_lo = 0.f, l_hi = 0.f;
    float acc[NFV][4];
#pragma unroll
    for (int nf = 0; nf < NFV; nf++)
#pragma unroll
        for (int i = 0; i < 4; i++) acc[nf][i] = 0.f;

    auto issue_tile = [&](int it, int nb) {
        int s0t = it * TS;
        unsigned kb = sbase + A_OFF_K0 + nb * 14336;
        unsigned vb = sbase + A_OFF_V0 + nb * 6656;
        for (int i = tid; i < 768; i += 256) {            // K: 32 x 24 chunks
            int c = i / 24, f = i - c * 24;
            int s = s0t + c;
            int ts = (s < Tq) ? s : outcell[b * EXPq + (s - Tq)];
            cpa16(kb + c * 448 + f * 16, &g_Kb[((b * Tq + ts) * Hq + h) * 24 + f]);
        }
        for (int i = tid; i < 384; i += 256) {            // V: 32 x 12 chunks
            int c = i / 12, f = i - c * 12;
            int s = s0t + c;
            int ts = (s < Tq) ? s : outcell[b * EXPq + (s - Tq)];
            const char* src = (const char*)&g_Vh[((b * Tq + ts) * Hq + h) * 48] + f * 16;
            cpa16(vb + c * VROW + f * 16, src);
        }
        unsigned bb = sbase + A_OFF_B0 + nb * 18432;
        unsigned lb = sbase + A_OFF_L0 + nb * 18432;
        const float* bsrc = &bias[((b * Hq + h) * Tq + t0) * Sq + s0t];
        const float* lsrc = &law [(b * Tq + t0) * Sq + s0t];
        for (int i = tid; i < 1024; i += 256) {
            int r = i >> 3, f = i & 7;
            cpa16(bb + r * (BLst * 4) + f * 16, bsrc + r * Sq + f * 4);
            cpa16(lb + r * (BLst * 4) + f * 16, lsrc + r * Sq + f * 4);
        }
        if (tid < TS) {
            int s = s0t + tid;
            sDead[nb * 32 + tid] =
                (s < Tq) ? kpm[b * Tq + s] : emask[b * EXPq + (s - Tq)];
        }
    };

    issue_tile(0, 0);
    cpa_commit();

    for (int it = 0; it < Sq / TS; it++) {
        const int cur = it & 1;
        if (it + 1 < Sq / TS) { issue_tile(it + 1, cur ^ 1); cpa_commit(); cpa_wait1(); }
        else                  { cpa_wait0(); }
        __syncthreads();

        const uint4* sKb = (const uint4*)(smembuf + A_OFF_K0 + cur * 14336);
        const unsigned vB = sbase + A_OFF_V0 + cur * 6656;
        const float* sB  = (const float*)(smembuf + A_OFF_B0 + cur * 18432);
        const float* sL  = (const float*)(smembuf + A_OFF_L0 + cur * 18432);

        // ---- scores: C[16x32] per warp, 3xBF16 k16
        float sc[4][4];
#pragma unroll
        for (int nf = 0; nf < 4; nf++)
#pragma unroll
            for (int i = 0; i < 4; i++) sc[nf][i] = 0.f;
#pragma unroll
        for (int ks = 0; ks < KS16; ks++) {
#pragma unroll
            for (int nf = 0; nf < 4; nf++) {
                uint4 bb = sKb[(nf * 8 + gid) * KBst + ks * 4 + tig];
                mma_bf16(sc[nf], qh[ks][0], qh[ks][1], qh[ks][2], qh[ks][3], bb.x, bb.y);
                mma_bf16(sc[nf], ql[ks][0], ql[ks][1], ql[ks][2], ql[ks][3], bb.x, bb.y);
                mma_bf16(sc[nf], qh[ks][0], qh[ks][1], qh[ks][2], qh[ks][3], bb.z, bb.w);
            }
        }

        // ---- bias + masks + online softmax (LDS-only operands)
        float pw[4][4];
        float lmax_lo = -3.0e38f, lmax_hi = -3.0e38f;
#pragma unroll
        for (int nf = 0; nf < 4; nf++) {
            int colL = nf * 8 + 2 * tig;
            float2 blo = *(const float2*)&sB[rlo * BLst + colL];
            float2 bhi = *(const float2*)&sB[rhi * BLst + colL];
            float2 wlo = *(const float2*)&sL[rlo * BLst + colL];
            float2 whi = *(const float2*)&sL[rhi * BLst + colL];
            unsigned char d0 = sDead[cur * 32 + colL], d1 = sDead[cur * 32 + colL + 1];

            float x, lw;
            x = sc[nf][0] + blo.x; lw = wlo.x;
            if (d0 || lw <= 1e-5f) { x = -3.0e38f; lw = 0.f; }
            sc[nf][0] = x; pw[nf][0] = lw; lmax_lo = fmaxf(lmax_lo, x);
            x = sc[nf][1] + blo.y; lw = wlo.y;
            if (d1 || lw <= 1e-5f) { x = -3.0e38f; lw = 0.f; }
            sc[nf][1] = x; pw[nf][1] = lw; lmax_lo = fmaxf(lmax_lo, x);
            x = sc[nf][2] + bhi.x; lw = whi.x;
            if (d0 || lw <= 1e-5f) { x = -3.0e38f; lw = 0.f; }
            sc[nf][2] = x; pw[nf][2] = lw; lmax_hi = fmaxf(lmax_hi, x);
            x = sc[nf][3] + bhi.y; lw = whi.y;
            if (d1 || lw <= 1e-5f) { x = -3.0e38f; lw = 0.f; }
            sc[nf][3] = x; pw[nf][3] = lw; lmax_hi = fmaxf(lmax_hi, x);
        }
#pragma unroll
        for (int o = 1; o < 4; o <<= 1) {
            lmax_lo = fmaxf(lmax_lo, __shfl_xor_sync(0xffffffffu, lmax_lo, o));
            lmax_hi = fmaxf(lmax_hi, __shfl_xor_sync(0xffffffffu, lmax_hi, o));
        }
        float nm_lo = fmaxf(m_lo, lmax_lo), nm_hi = fmaxf(m_hi, lmax_hi);
        float sl_lo = __expf(m_lo - nm_lo),  sl_hi = __expf(m_hi - nm_hi);
        m_lo = nm_lo; m_hi = nm_hi;

        // ---- P = exp(w-m)*law, packed fp16 hi/lo pairs in registers.
        unsigned pH[4][2], pL[4][2];
        float es_lo = 0.f, es_hi = 0.f;
#pragma unroll
        for (int nf = 0; nf < 4; nf++) {
            float e0 = __expf(sc[nf][0] - nm_lo); es_lo += e0;
            float e1 = __expf(sc[nf][1] - nm_lo); es_lo += e1;
            float e2 = __expf(sc[nf][2] - nm_hi); es_hi += e2;
            float e3 = __expf(sc[nf][3] - nm_hi); es_hi += e3;
            float p0 = e0 * pw[nf][0], p1 = e1 * pw[nf][1];
            float p2 = e2 * pw[nf][2], p3 = e3 * pw[nf][3];
            splitpack16(p0, p1, pH[nf][0], pL[nf][0]);   // rlo pair
            splitpack16(p2, p3, pH[nf][1], pL[nf][1]);   // rhi pair
        }
#pragma unroll
        for (int o = 1; o < 4; o <<= 1) {
            es_lo += __shfl_xor_sync(0xffffffffu, es_lo, o);
            es_hi += __shfl_xor_sync(0xffffffffu, es_hi, o);
        }
        l_lo = l_lo * sl_lo + es_lo;
        l_hi = l_hi * sl_hi + es_hi;
#pragma unroll
        for (int nf = 0; nf < NFV; nf++) {
            acc[nf][0] *= sl_lo; acc[nf][1] *= sl_lo;
            acc[nf][2] *= sl_hi; acc[nf][3] *= sl_hi;
        }

        // ---- PV: acc[16x96] += (Ph+Pl)[16x32] * Vh[32x96], fp16 k16 via ldmatrix
#pragma unroll
        for (int ks2 = 0; ks2 < 2; ks2++) {
            unsigned ah0 = pH[2 * ks2][0],     ah1 = pH[2 * ks2][1];
            unsigned ah2 = pH[2 * ks2 + 1][0], ah3 = pH[2 * ks2 + 1][1];
            unsigned al0 = pL[2 * ks2][0],     al1 = pL[2 * ks2][1];
            unsigned al2 = pL[2 * ks2 + 1][0], al3 = pL[2 * ks2 + 1][1];
            unsigned abase = vB + (16 * ks2 + vrow) * VROW + ncb * 2;
#pragma unroll
            for (int j = 0; j < 6; j++) {
                uint4 vh;
                ldsm4t(vh, abase + j * 32);
                mma_f16(acc[2 * j],     ah0, ah1, ah2, ah3, vh.x, vh.y);
                mma_f16(acc[2 * j],     al0, al1, al2, al3, vh.x, vh.y);
                mma_f16(acc[2 * j + 1], ah0, ah1, ah2, ah3, vh.z, vh.w);
                mma_f16(acc[2 * j + 1], al0, al1, al2, al3, vh.z, vh.w);
            }
        }
        __syncthreads();                       // all reads of buf[cur] done
    }

    float rl_lo = (l_lo > 0.f) ? 1.f / l_lo : 0.f;
    float rl_hi = (l_hi > 0.f) ? 1.f / l_hi : 0.f;
#pragma unroll
    for (int nf = 0; nf < NFV; nf++) {
        int d = nf * 8 + 2 * tig;
        int p = d >> 5, j = d & 31;
        *(float2*)&g_attn[((b * Tq + tlo) * Pq + p) * HIDq + h * 32 + j] =
            make_float2(acc[nf][0] * rl_lo, acc[nf][1] * rl_lo);
        *(float2*)&g_attn[((b * Tq + thi) * Pq + p) * HIDq + h * 32 + j] =
            make_float2(acc[nf][2] * rl_hi, acc[nf][3] * rl_hi);
    }
}

// ---------------------------------------------------------------------------
// inv + scale + bf16 hi/lo split: X = attn*lnw*inv -> k16 fragment rows.
// ---------------------------------------------------------------------------
__global__ __launch_bounds__(128) void inv_split_kernel(const float* __restrict__ lnw)
{
    const int bt = blockIdx.x;
    const float* a = &g_attn[bt * Pq * HIDq];
    const int tid = threadIdx.x;
    float s = 0.f;
    for (int i = tid; i < (Pq * HIDq) / 4; i += 128) {
        float4 x = *(const float4*)&a[i * 4];
        s = fmaf(x.x, x.x, s); s = fmaf(x.y, x.y, s);
        s = fmaf(x.z, x.z, s); s = fmaf(x.w, x.w, s);
    }
#pragma unroll
    for (int o = 16; o; o >>= 1) s += __shfl_xor_sync(0xffffffffu, s, o);
    __shared__ float ws[4];
    __shared__ float sInv;
    if ((tid & 31) == 0) ws[tid >> 5] = s;
    __syncthreads();
    if (tid == 0) {
        float tot = ws[0] + ws[1] + ws[2] + ws[3];
        sInv = rsqrtf(tot * (1.0f / (float)HIDq) + 1e-3f);
    }
    __syncthreads();
    const float inv = sInv;

    for (int u = tid; u < Pq * 128; u += 128) {
        int p = u >> 7, j = u & 127;
        int ks = j >> 2, tg = j & 3;
        int d0 = ks * 16 + 2 * tg;
        const float* ap = &a[p * HIDq + d0];
        float x0 = ap[0] * lnw[d0]     * inv;
        float x1 = ap[1] * lnw[d0 + 1] * inv;
        float x8 = ap[8] * lnw[d0 + 8] * inv;
        float x9 = ap[9] * lnw[d0 + 9] * inv;
        unsigned h0, l0, h1, l1;
        splitpack(x0, x1, h0, l0);
        splitpack(x8, x9, h1, l1);
        g_Xb[(bt * Pq + p) * 128 + j] = make_uint4(h0, h1, l0, l1);
    }
}

// ---------------------------------------------------------------------------
// Projection GEMM: out[m][n] = sum_k X[m][k]*W[n][k], 3xBF16 k16.
// ---------------------------------------------------------------------------
__global__ __launch_bounds__(256, 1) void proj_kernel(float* __restrict__ out)
{
    extern __shared__ __align__(16) char smembuf[];
    unsigned sbase;
    { unsigned long long p0 = __cvta_generic_to_shared(smembuf); sbase = (unsigned)p0; }

    const int bm = blockIdx.x, bn = blockIdx.y;
    const int tid  = threadIdx.x;
    const int warp = tid >> 5, lane = tid & 31;
    const int gid  = lane >> 2, tig = lane & 3;
    const int wm = warp & 3, wn = warp >> 2;

    auto load_chunk = [&](int c, int nb) {
        unsigned xb = sbase + P_OFF_X0 + nb * 20480;
        for (int i = tid; i < 1024; i += 256) {
            int r = i >> 4, f = i & 15;
            cpa16(xb + (r * P_STR + f) * 16, &g_Xb[(bm * 64 + r) * 128 + c * 16 + f]);
        }
        unsigned wb = sbase + P_OFF_W0 + nb * 40960;
        for (int i = tid; i < 2048; i += 256) {
            int r = i >> 4, f = i & 15;
            cpa16(wb + (r * P_STR + f) * 16, &g_Wb[(bn * 128 + r) * 128 + c * 16 + f]);
        }
    };

    float acc[8][4];
#pragma unroll
    for (int nf = 0; nf < 8; nf++)
#pragma unroll
        for (int i = 0; i < 4; i++) acc[nf][i] = 0.f;

    load_chunk(0, 0);
    cpa_commit();

    for (int c = 0; c < 8; c++) {
        const int cur = c & 1;
        if (c + 1 < 8) { load_chunk(c + 1, cur ^ 1); cpa_commit(); cpa_wait1(); }
        else           { cpa_wait0(); }
        __syncthreads();

        const uint4* Xs = (const uint4*)(smembuf + P_OFF_X0 + cur * 20480);
        const uint4* Wt = (const uint4*)(smembuf + P_OFF_W0 + cur * 40960);
#pragma unroll
        for (int ks = 0; ks < 4; ks++) {
            uint4 aL = Xs[(wm * 16 + gid)     * P_STR + ks * 4 + tig];
            uint4 aH = Xs[(wm * 16 + gid + 8) * P_STR + ks * 4 + tig];
#pragma unroll
            for (int nf = 0; nf < 8; nf++) {
                uint4 w4 = Wt[(wn * 64 + nf * 8 + gid) * P_STR + ks * 4 + tig];
                mma_bf16(acc[nf], aL.x, aH.x, aL.y, aH.y, w4.x, w4.y);
                mma_bf16(acc[nf], aL.z, aH.z, aL.w, aH.w, w4.x, w4.y);
                mma_bf16(acc[nf], aL.x, aH.x, aL.y, aH.y, w4.z, w4.w);
            }
        }
        __syncthreads();
    }

    const int mlo = bm * 64 + wm * 16 + gid;
    const int mhi = mlo + 8;
#pragma unroll
    for (int nf = 0; nf < 8; nf++) {
        int col = bn * 128 + wn * 64 + nf * 8 + 2 * tig;
        *(float2*)&out[mlo * HIDq + col] = make_float2(acc[nf][0], acc[nf][1]);
        *(float2*)&out[mhi * HIDq + col] = make_float2(acc[nf][2], acc[nf][3]);
    }
}

// ---------------------------------------------------------------------------
extern "C" void kernel_launch(void* const* d_in, const int* in_sizes, int n_in,
                              void* d_out, int out_size)
{
    const float* q    = (const float*)d_in[0];
    const float* k    = (const float*)d_in[1];
    const float* v    = (const float*)d_in[2];
    const float* bias = (const float*)d_in[3];
    const unsigned char* kpm   = (const unsigned char*)d_in[4];
    const int*   outcell       = (const int*)d_in[5];
    const float* law  = (const float*)d_in[6];
    const unsigned char* emask = (const unsigned char*)d_in[7];
    const float* W    = (const float*)d_in[8];
    const float* lnw  = (const float*)d_in[9];
    float* out = (float*)d_out;

    cudaFuncSetAttribute(attn_kernel,
        cudaFuncAttributeMaxDynamicSharedMemorySize, A_SMEM);
    cudaFuncSetAttribute(proj_kernel,
        cudaFuncAttributeMaxDynamicSharedMemorySize, P_SMEM);

    int units = Bq * Tq * Hq * 48;
    presplit_kernel<<<(units + 255) / 256, 256>>>(k, v);
    presplit_w_kernel<<<(HIDq * 128 + 255) / 256, 256>>>(W);

    dim3 g1(Tq / TT, Hq, Bq);
    attn_kernel<<<g1, 256, A_SMEM>>>(q, bias, kpm, outcell, law, emask);

    inv_split_kernel<<<Bq * Tq, 128>>>(lnw);

    dim3 g3((Bq * Tq * Pq) / 64, HIDq / 128);
    proj_kernel<<<g3, 256, P_SMEM>>>(out);
}